// round 11
// baseline (speedup 1.0000x reference)
#include <cuda_runtime.h>
#include <cuda_fp16.h>
#include <cstdint>
#include <cstddef>

// ---------------- problem constants ----------------
#define BB   2
#define TT   2048
#define DD   1024
#define HH   16
#define KH   64          // D / H
#define NPJ  3088        // 3*D + H
#define MMR  4096        // B*T
#define SCALE_V 0.03125f // 1/sqrt(D)
#define SCH  128         // scan chunk
#define SLB  128         // scan lookback (err <= e^-12.8 ~ 2.7e-6)
#define NCH  (TT/SCH)    // 16

// ---------------- scratch (__device__ globals; no allocations) ----------------
__device__ __half g_xh [MMR*DD];
__device__ __half g_wih[NPJ*DD];
__device__ __half g_woh[DD*DD];           // plain fp16 W_out (unused by GEMM2 now; kept tiny path-free)
__device__ __half g_wsh[2*DD*DD];         // per-batch GroupNorm-scaled W_out (fp16)
__device__ float  g_cvec[2*DD];           // per-batch GN offset folded through W_out
__device__ float  g_proj[(size_t)MMR*NPJ]; // (B*T, 3D+H)
__device__ float  g_vbuf[MMR*DD];          // (B,H,T,K) gated v * scale
__device__ float  g_adec[BB*HH*TT];        // (B,H,T) decay multiplier
__device__ __half g_gh [MMR*DD];           // raw g = silu(r)*y in fp16
__device__ float2 g_psum[BB*HH*NCH];       // partial (sum, sumsq) per group-chunk
__device__ float2 g_stats[BB*HH];          // (mean, rstd)

// ---------------- fp32 -> fp16 (float4 vectorized) ----------------
__global__ void cvt_kernel(const float4* __restrict__ in, __half2* __restrict__ hi, int n4) {
    int i = blockIdx.x * blockDim.x + threadIdx.x;
    if (i >= n4) return;
    float4 v = in[i];
    hi[2*i]   = __halves2half2(__float2half_rn(v.x), __float2half_rn(v.y));
    hi[2*i+1] = __halves2half2(__float2half_rn(v.z), __float2half_rn(v.w));
}

// ---------------- single-pass fp16 GEMM: C = A*B^T (+cv) (fp32 accum) ----------------
// 128x128 CTA tile, 256 threads, 4x2 warps of 32x64 (best-measured config).
// If cv != nullptr: B is chosen per batch (rows 0..2047 -> B, rest -> Balt) and
// cv[batch*N + n] is added in the epilogue (GroupNorm folded into GEMM2).
#define BM 128
#define BN 128
#define BK 32
#define AST 40                       // padded smem row stride in halves
#define NSTG 4                       // cp.async pipeline depth
#define STGA (BM*AST*2)              // 10240 bytes per A stage
#define STGB (BN*AST*2)              // 10240 bytes per B stage
#define STG  (STGA+STGB)             // 20480 bytes per stage
#define GSMEM (NSTG*STG)             // 81920 bytes dynamic smem

__device__ __forceinline__ void ldsm4(uint32_t& r0, uint32_t& r1, uint32_t& r2, uint32_t& r3,
                                      uint32_t addr) {
    asm volatile("ldmatrix.sync.aligned.m8n8.x4.shared.b16 {%0,%1,%2,%3}, [%4];"
                 : "=r"(r0), "=r"(r1), "=r"(r2), "=r"(r3) : "r"(addr));
}

extern __shared__ char gsm[];

__global__ void __launch_bounds__(256, 2) gemm1p_kernel(
    const __half* __restrict__ A, const __half* __restrict__ B0,
    const __half* __restrict__ Balt, const float* __restrict__ cv,
    float* __restrict__ C, int M, int N, int K)
{
    const uint32_t sbase = (uint32_t)__cvta_generic_to_shared(gsm);

    const int tid  = threadIdx.x;
    const int warp = tid >> 5, lane = tid & 31;
    const int wm = warp & 3, wn = warp >> 2;      // 4 x 2 warp grid
    const int g  = lane >> 2, tg = lane & 3;
    const int bm = blockIdx.y * BM;
    const int bn = blockIdx.x * BN;
    const int batch = bm >> 11;                   // 2048 rows per batch
    const __half* B = (cv && batch) ? Balt : B0;
    const float* cvb = cv ? (cv + batch * N) : nullptr;
    const int KT = K / BK;
    const int lr = tid >> 2;          // 0..63
    const int lc = (tid & 3) * 8;     // 0,8,16,24 halves

    const uint32_t dA0 = (lr * AST + lc) * 2;
    const uint32_t dA1 = ((lr + 64) * AST + lc) * 2;

    const int n0 = bn + lr, n1 = bn + lr + 64;
    const int p0 = (n0 < N) ? 16 : 0;
    const int p1 = (n1 < N) ? 16 : 0;
    const size_t aoff0 = (size_t)(bm + lr) * K + lc;
    const size_t aoff1 = (size_t)(bm + lr + 64) * K + lc;
    const size_t boff0 = (size_t)((n0 < N) ? n0 : N - 1) * K + lc;
    const size_t boff1 = (size_t)((n1 < N) ? n1 : N - 1) * K + lc;

    auto ISSUE = [&](int chunk) {
        int kk = chunk * BK;
        uint32_t st = sbase + (chunk & (NSTG - 1)) * STG;
        asm volatile("cp.async.cg.shared.global [%0], [%1], 16;\n"
                     :: "r"(st + dA0), "l"(A + aoff0 + kk));
        asm volatile("cp.async.cg.shared.global [%0], [%1], 16;\n"
                     :: "r"(st + dA1), "l"(A + aoff1 + kk));
        asm volatile("cp.async.cg.shared.global [%0], [%1], 16, %2;\n"
                     :: "r"(st + STGA + dA0), "l"(B + boff0 + kk), "r"(p0));
        asm volatile("cp.async.cg.shared.global [%0], [%1], 16, %2;\n"
                     :: "r"(st + STGA + dA1), "l"(B + boff1 + kk), "r"(p1));
        asm volatile("cp.async.commit_group;\n");
    };

    float acc[2][8][4];
#pragma unroll
    for (int i = 0; i < 2; i++)
#pragma unroll
        for (int j = 0; j < 8; j++)
#pragma unroll
            for (int q = 0; q < 4; q++) acc[i][j][q] = 0.f;

    const uint32_t a_row = wm * 32 + (lane & 15);
    const uint32_t a_ko  = (lane >> 4) << 3;
    const uint32_t b_row = wn * 64 + (lane & 7) + ((lane & 16) >> 1);
    const uint32_t b_ko  = (lane & 8);

    ISSUE(0); ISSUE(1); ISSUE(2);

    for (int it = 0; it < KT; ++it) {
        const int rem = KT - 1 - it;
        if (rem >= 2)      asm volatile("cp.async.wait_group 2;\n" ::: "memory");
        else if (rem == 1) asm volatile("cp.async.wait_group 1;\n" ::: "memory");
        else               asm volatile("cp.async.wait_group 0;\n" ::: "memory");
        __syncthreads();
        if (it + 3 < KT) ISSUE(it + 3);

        const uint32_t st = sbase + (it & (NSTG - 1)) * STG;
        const uint32_t Ab = st;
        const uint32_t Bb = st + STGA;
#pragma unroll
        for (int ks = 0; ks < 2; ++ks) {
            uint32_t ra[2][4];
#pragma unroll
            for (int mi = 0; mi < 2; ++mi) {
                uint32_t addr = Ab + ((a_row + mi * 16) * AST + ks * 16 + a_ko) * 2;
                ldsm4(ra[mi][0], ra[mi][1], ra[mi][2], ra[mi][3], addr);
            }
            uint32_t rb[8][2];
#pragma unroll
            for (int ni2 = 0; ni2 < 4; ++ni2) {
                uint32_t addr = Bb + ((b_row + ni2 * 16) * AST + ks * 16 + b_ko) * 2;
                ldsm4(rb[2*ni2][0], rb[2*ni2][1], rb[2*ni2+1][0], rb[2*ni2+1][1], addr);
            }
#pragma unroll
            for (int mi = 0; mi < 2; ++mi)
#pragma unroll
                for (int ni = 0; ni < 8; ++ni)
                    asm volatile(
                        "mma.sync.aligned.m16n8k16.row.col.f32.f16.f16.f32 "
                        "{%0,%1,%2,%3},{%4,%5,%6,%7},{%8,%9},{%0,%1,%2,%3};\n"
                        : "+f"(acc[mi][ni][0]), "+f"(acc[mi][ni][1]),
                          "+f"(acc[mi][ni][2]), "+f"(acc[mi][ni][3])
                        : "r"(ra[mi][0]), "r"(ra[mi][1]), "r"(ra[mi][2]), "r"(ra[mi][3]),
                          "r"(rb[ni][0]), "r"(rb[ni][1]));
        }
    }

#pragma unroll
    for (int mi = 0; mi < 2; ++mi) {
        int r0 = bm + wm * 32 + mi * 16 + g;
#pragma unroll
        for (int ni = 0; ni < 8; ++ni) {
            int c0 = bn + wn * 64 + ni * 8 + tg * 2;
            if (c0 < N) {
                float2 v0 = make_float2(acc[mi][ni][0], acc[mi][ni][1]);
                float2 v1 = make_float2(acc[mi][ni][2], acc[mi][ni][3]);
                if (cvb) {
                    float2 cc = *(const float2*)(cvb + c0);
                    v0.x += cc.x; v0.y += cc.y; v1.x += cc.x; v1.y += cc.y;
                }
                *(float2*)(C + (size_t)r0       * N + c0) = v0;
                *(float2*)(C + (size_t)(r0 + 8) * N + c0) = v1;
            }
        }
    }
}

// ---------------- gate: shifted depthwise conv + silu gating + repack (x4) ----------------
__global__ void gate_kernel(const float* __restrict__ conv_w, const float* __restrict__ conv_b) {
    int i4 = blockIdx.x * blockDim.x + threadIdx.x;
    if (i4 >= MMR * DD / 4) return;
    int idx = i4 * 4;
    int d  = idx & (DD - 1);
    int bt = idx >> 10;
    int t  = bt & (TT - 1);
    int b  = bt >> 11;

    float4 cw[4];
#pragma unroll
    for (int u = 0; u < 4; ++u) cw[u] = *(const float4*)(conv_w + (d + u) * 4);
    float4 cb = *(const float4*)(conv_b + d);
    float ko[4] = {cb.x, cb.y, cb.z, cb.w};

#pragma unroll
    for (int j = 0; j < 4; ++j) {
        int tt = t - 6 + j;
        if (tt >= 0) {
            float4 kv = *(const float4*)(g_proj + (size_t)(b * TT + tt) * NPJ + 2 * DD + d);
            ko[0] = fmaf(((const float*)&cw[0])[j], kv.x, ko[0]);
            ko[1] = fmaf(((const float*)&cw[1])[j], kv.y, ko[1]);
            ko[2] = fmaf(((const float*)&cw[2])[j], kv.z, ko[2]);
            ko[3] = fmaf(((const float*)&cw[3])[j], kv.w, ko[3]);
        }
    }
    float4 v4 = *(const float4*)(g_proj + (size_t)bt * NPJ + DD + d);
    float ov[4];
    const float* vv = (const float*)&v4;
#pragma unroll
    for (int u = 0; u < 4; ++u) {
        float sk = ko[u] / (1.f + __expf(-ko[u]));
        ov[u] = vv[u] * sk * SCALE_V;
    }
    int h = d >> 6, kk = d & 63;
    *(float4*)(g_vbuf + ((size_t)(b * HH + h) * TT + t) * KH + kk) =
        make_float4(ov[0], ov[1], ov[2], ov[3]);
}

// ---------------- decay multiplier per (b,h,t) ----------------
__global__ void decay_kernel(const float* __restrict__ dp) {
    int idx = blockIdx.x * blockDim.x + threadIdx.x;
    if (idx >= BB * TT * HH) return;
    int h  = idx & (HH - 1);
    int bt = idx >> 4;
    float wv = g_proj[(size_t)bt * NPJ + 3 * DD + h];
    float gg = 1.f / (1.f + expf(-(dp[h] + wv)));
    float a  = expf(-8.f * (1.f - gg) - 0.1f);           // exp(log_decay), <= exp(-0.1)
    int b = bt >> 11, t = bt & (TT - 1);
    g_adec[(b * HH + h) * TT + t] = a;
}

// ---------------- chunked scan: fused silu(r)*y, fp16 g output, GN partials ----------------
__global__ void scan_kernel() {
    const int c  = blockIdx.x & (NCH - 1);
    const int bh = blockIdx.x >> 4;
    const int b  = bh >> 4, h = bh & (HH - 1);
    const int k  = threadIdx.x;                          // 0..63
    const int t0 = c * SCH;
    int s0 = t0 - SLB; if (s0 < 0) s0 = 0;
    const float* vp = g_vbuf + (size_t)bh * TT * KH;
    const float* ap = g_adec + (size_t)bh * TT;
    const int col = h * KH + k;

    float y = 0.f;
    for (int s = s0; s < t0; s += 4) {                   // lookback warm-up
        float4 a4 = *(const float4*)(ap + s);
        float v0 = vp[(size_t)(s + 0) * KH + k];
        float v1 = vp[(size_t)(s + 1) * KH + k];
        float v2 = vp[(size_t)(s + 2) * KH + k];
        float v3 = vp[(size_t)(s + 3) * KH + k];
        y = fmaf(a4.x, y, v0);
        y = fmaf(a4.y, y, v1);
        y = fmaf(a4.z, y, v2);
        y = fmaf(a4.w, y, v3);
    }

    float s1 = 0.f, s2 = 0.f;
    for (int sm = t0; sm < t0 + SCH; sm += 4) {
        float4 a4 = *(const float4*)(ap + sm);
        float aa[4] = {a4.x, a4.y, a4.z, a4.w};
        float vv[4], rr[4];
#pragma unroll
        for (int j = 0; j < 4; ++j) {
            vv[j] = vp[(size_t)(sm + j) * KH + k];
            rr[j] = g_proj[(size_t)(b * TT + sm + j) * NPJ + col];
        }
#pragma unroll
        for (int j = 0; j < 4; ++j) {
            y = fmaf(aa[j], y, vv[j]);
            float r  = rr[j];
            float sr = r / (1.f + __expf(-r));
            float gv = sr * y;
            g_gh[(size_t)(b * TT + sm + j) * DD + col] = __float2half_rn(gv);
            s1 += gv;
            s2 = fmaf(gv, gv, s2);
        }
    }

    __shared__ float rs1[64], rs2[64];
    rs1[k] = s1; rs2[k] = s2;
    __syncthreads();
    for (int off = 32; off > 0; off >>= 1) {
        if (k < off) { rs1[k] += rs1[k + off]; rs2[k] += rs2[k + off]; }
        __syncthreads();
    }
    if (k == 0) g_psum[bh * NCH + c] = make_float2(rs1[0], rs2[0]);
}

// ---------------- GroupNorm statistics (deterministic combine) ----------------
__global__ void stats_kernel() {
    int gi = threadIdx.x;
    if (gi >= BB * HH) return;
    float s1 = 0.f, s2 = 0.f;
    for (int c = 0; c < NCH; ++c) {
        float2 p = g_psum[gi * NCH + c];
        s1 += p.x; s2 += p.y;
    }
    const float inv = 1.f / (float)(KH * TT);
    float mean = s1 * inv;
    float var  = s2 * inv - mean * mean;
    g_stats[gi] = make_float2(mean, rsqrtf(var + 1e-5f));
}

// ---------------- build per-batch GN-scaled W_out (fp16): W_s[b][n][d] = W[n][d]*rstd[b,h]*gn_w[d]
__global__ void wscale_kernel(const float* __restrict__ W_out, const float* __restrict__ gn_w) {
    int i4 = blockIdx.x * blockDim.x + threadIdx.x;
    if (i4 >= DD * DD / 4) return;
    int idx = i4 * 4;
    int d = idx & (DD - 1);
    int h = d >> 6;
    float4 w4 = *(const float4*)(W_out + idx);
    float4 g4 = *(const float4*)(gn_w + d);
#pragma unroll
    for (int b = 0; b < BB; ++b) {
        float rs = g_stats[b * HH + h].y;
        __half2* ph = (__half2*)(g_wsh + (size_t)b * DD * DD + idx);
        ph[0] = __halves2half2(__float2half_rn(w4.x * rs * g4.x),
                               __float2half_rn(w4.y * rs * g4.y));
        ph[1] = __halves2half2(__float2half_rn(w4.z * rs * g4.z),
                               __float2half_rn(w4.w * rs * g4.w));
    }
}

// ---------------- per-batch GN offset through W_out: c[b][n] = sum_d (gn_b - mu*rstd*gn_w)_d W[n,d]
__global__ void cvec_kernel(const float* __restrict__ W_out,
                            const float* __restrict__ gn_w, const float* __restrict__ gn_b) {
    int gw = blockIdx.x * (blockDim.x >> 5) + (threadIdx.x >> 5);
    if (gw >= BB * DD) return;
    int b = gw >> 10, n = gw & (DD - 1);
    int lane = threadIdx.x & 31;
    float s = 0.f;
    for (int d = lane; d < DD; d += 32) {
        float2 st = g_stats[b * HH + (d >> 6)];
        float off = gn_b[d] - st.x * st.y * gn_w[d];
        s = fmaf(W_out[(size_t)n * DD + d], off, s);
    }
#pragma unroll
    for (int o = 16; o > 0; o >>= 1) s += __shfl_xor_sync(0xFFFFFFFFu, s, o);
    if (lane == 0) g_cvec[gw] = s;
}

// ---------------- launch ----------------
extern "C" void kernel_launch(void* const* d_in, const int* in_sizes, int n_in,
                              void* d_out, int out_size) {
    const float* x      = (const float*)d_in[0];
    const float* W_in   = (const float*)d_in[1];
    const float* conv_w = (const float*)d_in[2];
    const float* conv_b = (const float*)d_in[3];
    const float* dp     = (const float*)d_in[4];
    const float* gn_w   = (const float*)d_in[5];
    const float* gn_b   = (const float*)d_in[6];
    const float* W_out  = (const float*)d_in[7];
    float* out = (float*)d_out;
    (void)in_sizes; (void)n_in; (void)out_size;

    void *pxh, *pwih, *pproj, *pgh, *pwsh, *pcv;
    cudaGetSymbolAddress(&pxh,  g_xh);
    cudaGetSymbolAddress(&pwih, g_wih);
    cudaGetSymbolAddress(&pproj, g_proj);
    cudaGetSymbolAddress(&pgh,  g_gh);
    cudaGetSymbolAddress(&pwsh, g_wsh);
    cudaGetSymbolAddress(&pcv,  g_cvec);

    cudaFuncSetAttribute(gemm1p_kernel,
                         cudaFuncAttributeMaxDynamicSharedMemorySize, GSMEM);

    const int TPB = 256;
    cvt_kernel<<<(MMR*DD/4 + TPB-1)/TPB, TPB>>>((const float4*)x,    (__half2*)pxh,  MMR*DD/4);
    cvt_kernel<<<(NPJ*DD/4 + TPB-1)/TPB, TPB>>>((const float4*)W_in, (__half2*)pwih, NPJ*DD/4);

    // GEMM1: proj = x @ W_in^T (single-pass fp16, fp32 accum)
    dim3 gg1((NPJ + BN - 1)/BN, MMR/BM);
    gemm1p_kernel<<<gg1, 256, GSMEM>>>((__half*)pxh, (__half*)pwih,
                                       (__half*)pwih, nullptr,
                                       (float*)pproj, MMR, NPJ, DD);

    gate_kernel <<<(MMR*DD/4 + TPB-1)/TPB, TPB>>>(conv_w, conv_b);
    decay_kernel<<<(BB*TT*HH + TPB-1)/TPB, TPB>>>(dp);
    scan_kernel <<<BB*HH*NCH, 64>>>();
    stats_kernel<<<1, 32>>>();

    // fold GroupNorm into GEMM2 operands
    wscale_kernel<<<(DD*DD/4 + TPB-1)/TPB, TPB>>>(W_out, gn_w);
    cvec_kernel  <<<(BB*DD/8), 256>>>(W_out, gn_w, gn_b);

    // GEMM2: out = g @ (W_out * s_b)^T + c_b
    dim3 gg2(DD/BN, MMR/BM);
    gemm1p_kernel<<<gg2, 256, GSMEM>>>((__half*)pgh,
                                       (__half*)pwsh,                      // batch 0 weights
                                       (__half*)pwsh + (size_t)DD*DD,      // batch 1 weights
                                       (const float*)pcv,
                                       out, MMR, DD, DD);
}

// round 12
// speedup vs baseline: 1.1394x; 1.1394x over previous
#include <cuda_runtime.h>
#include <cuda_fp16.h>
#include <cstdint>
#include <cstddef>

// ---------------- problem constants ----------------
#define BB   2
#define TT   2048
#define DD   1024
#define HH   16
#define KH   64          // D / H
#define NPJ  3088        // 3*D + H
#define MMR  4096        // B*T
#define SCALE_V 0.03125f // 1/sqrt(D)
#define SCH  64          // scan chunk
#define SLB  128         // scan lookback (err <= e^-12.8 ~ 2.7e-6)
#define NCH  (TT/SCH)    // 32

// ---------------- scratch (__device__ globals; no allocations) ----------------
__device__ __half g_xh [MMR*DD];
__device__ __half g_wih[NPJ*DD];
__device__ __half g_woh[DD*DD];
__device__ float  g_proj[(size_t)MMR*NPJ]; // (B*T, 3D+H)
__device__ float  g_vbuf[MMR*DD];          // (B,H,T,K) gated v * scale
__device__ float  g_adec[BB*HH*TT];        // (B,H,T) decay multiplier
__device__ float  g_gbuf[MMR*DD];          // (B,T,D) silu(r)*y
__device__ __half g_gh [MMR*DD];
__device__ float2 g_psum[BB*HH*NCH];       // partial (sum, sumsq) per group-chunk
__device__ float2 g_stats[BB*HH];          // (mean, rstd)

// ---------------- fp32 -> fp16 (float4 vectorized) ----------------
__global__ void cvt_kernel(const float4* __restrict__ in, __half2* __restrict__ hi, int n4) {
    int i = blockIdx.x * blockDim.x + threadIdx.x;
    if (i >= n4) return;
    float4 v = in[i];
    hi[2*i]   = __halves2half2(__float2half_rn(v.x), __float2half_rn(v.y));
    hi[2*i+1] = __halves2half2(__float2half_rn(v.z), __float2half_rn(v.w));
}

// ---------------- single-pass fp16 GEMM: C = A*B^T (fp32 accum) ----------------
// Best-measured config: 128x128 CTA tile, 256 threads, 4x2 warps of 32x64.
#define BM 128
#define BN 128
#define BK 32
#define AST 40                       // padded smem row stride in halves
#define NSTG 4                       // cp.async pipeline depth
#define STGA (BM*AST*2)              // 10240 bytes per A stage
#define STGB (BN*AST*2)              // 10240 bytes per B stage
#define STG  (STGA+STGB)             // 20480 bytes per stage
#define GSMEM (NSTG*STG)             // 81920 bytes dynamic smem

__device__ __forceinline__ void ldsm4(uint32_t& r0, uint32_t& r1, uint32_t& r2, uint32_t& r3,
                                      uint32_t addr) {
    asm volatile("ldmatrix.sync.aligned.m8n8.x4.shared.b16 {%0,%1,%2,%3}, [%4];"
                 : "=r"(r0), "=r"(r1), "=r"(r2), "=r"(r3) : "r"(addr));
}

extern __shared__ char gsm[];

__global__ void __launch_bounds__(256, 2) gemm1p_kernel(
    const __half* __restrict__ A, const __half* __restrict__ B,
    float* __restrict__ C, int M, int N, int K)
{
    const uint32_t sbase = (uint32_t)__cvta_generic_to_shared(gsm);

    const int tid  = threadIdx.x;
    const int warp = tid >> 5, lane = tid & 31;
    const int wm = warp & 3, wn = warp >> 2;      // 4 x 2 warp grid
    const int g  = lane >> 2, tg = lane & 3;
    const int bm = blockIdx.y * BM;
    const int bn = blockIdx.x * BN;
    const int KT = K / BK;                        // total k-chunks (single pass)
    const int lr = tid >> 2;          // 0..63
    const int lc = (tid & 3) * 8;     // 0,8,16,24 halves

    const uint32_t dA0 = (lr * AST + lc) * 2;
    const uint32_t dA1 = ((lr + 64) * AST + lc) * 2;

    const int n0 = bn + lr, n1 = bn + lr + 64;
    const int p0 = (n0 < N) ? 16 : 0;
    const int p1 = (n1 < N) ? 16 : 0;
    const size_t aoff0 = (size_t)(bm + lr) * K + lc;
    const size_t aoff1 = (size_t)(bm + lr + 64) * K + lc;
    const size_t boff0 = (size_t)((n0 < N) ? n0 : N - 1) * K + lc;
    const size_t boff1 = (size_t)((n1 < N) ? n1 : N - 1) * K + lc;

    auto ISSUE = [&](int chunk) {
        int kk = chunk * BK;
        uint32_t st = sbase + (chunk & (NSTG - 1)) * STG;
        asm volatile("cp.async.cg.shared.global [%0], [%1], 16;\n"
                     :: "r"(st + dA0), "l"(A + aoff0 + kk));
        asm volatile("cp.async.cg.shared.global [%0], [%1], 16;\n"
                     :: "r"(st + dA1), "l"(A + aoff1 + kk));
        asm volatile("cp.async.cg.shared.global [%0], [%1], 16, %2;\n"
                     :: "r"(st + STGA + dA0), "l"(B + boff0 + kk), "r"(p0));
        asm volatile("cp.async.cg.shared.global [%0], [%1], 16, %2;\n"
                     :: "r"(st + STGA + dA1), "l"(B + boff1 + kk), "r"(p1));
        asm volatile("cp.async.commit_group;\n");
    };

    float acc[2][8][4];
#pragma unroll
    for (int i = 0; i < 2; i++)
#pragma unroll
        for (int j = 0; j < 8; j++)
#pragma unroll
            for (int q = 0; q < 4; q++) acc[i][j][q] = 0.f;

    // ldmatrix per-lane address components
    const uint32_t a_row = wm * 32 + (lane & 15);
    const uint32_t a_ko  = (lane >> 4) << 3;
    const uint32_t b_row = wn * 64 + (lane & 7) + ((lane & 16) >> 1);
    const uint32_t b_ko  = (lane & 8);

    ISSUE(0); ISSUE(1); ISSUE(2);

    for (int it = 0; it < KT; ++it) {
        const int rem = KT - 1 - it;
        if (rem >= 2)      asm volatile("cp.async.wait_group 2;\n" ::: "memory");
        else if (rem == 1) asm volatile("cp.async.wait_group 1;\n" ::: "memory");
        else               asm volatile("cp.async.wait_group 0;\n" ::: "memory");
        __syncthreads();
        if (it + 3 < KT) ISSUE(it + 3);

        const uint32_t st = sbase + (it & (NSTG - 1)) * STG;
        const uint32_t Ab = st;
        const uint32_t Bb = st + STGA;
#pragma unroll
        for (int ks = 0; ks < 2; ++ks) {
            uint32_t ra[2][4];
#pragma unroll
            for (int mi = 0; mi < 2; ++mi) {
                uint32_t addr = Ab + ((a_row + mi * 16) * AST + ks * 16 + a_ko) * 2;
                ldsm4(ra[mi][0], ra[mi][1], ra[mi][2], ra[mi][3], addr);
            }
            uint32_t rb[8][2];
#pragma unroll
            for (int ni2 = 0; ni2 < 4; ++ni2) {
                uint32_t addr = Bb + ((b_row + ni2 * 16) * AST + ks * 16 + b_ko) * 2;
                ldsm4(rb[2*ni2][0], rb[2*ni2][1], rb[2*ni2+1][0], rb[2*ni2+1][1], addr);
            }
#pragma unroll
            for (int mi = 0; mi < 2; ++mi)
#pragma unroll
                for (int ni = 0; ni < 8; ++ni)
                    asm volatile(
                        "mma.sync.aligned.m16n8k16.row.col.f32.f16.f16.f32 "
                        "{%0,%1,%2,%3},{%4,%5,%6,%7},{%8,%9},{%0,%1,%2,%3};\n"
                        : "+f"(acc[mi][ni][0]), "+f"(acc[mi][ni][1]),
                          "+f"(acc[mi][ni][2]), "+f"(acc[mi][ni][3])
                        : "r"(ra[mi][0]), "r"(ra[mi][1]), "r"(ra[mi][2]), "r"(ra[mi][3]),
                          "r"(rb[ni][0]), "r"(rb[ni][1]));
        }
    }

#pragma unroll
    for (int mi = 0; mi < 2; ++mi) {
        int r0 = bm + wm * 32 + mi * 16 + g;
#pragma unroll
        for (int ni = 0; ni < 8; ++ni) {
            int c0 = bn + wn * 64 + ni * 8 + tg * 2;
            if (c0 < N) {
                *(float2*)(C + (size_t)r0       * N + c0) = make_float2(acc[mi][ni][0], acc[mi][ni][1]);
                *(float2*)(C + (size_t)(r0 + 8) * N + c0) = make_float2(acc[mi][ni][2], acc[mi][ni][3]);
            }
        }
    }
}

// ---------------- gate: shifted depthwise conv + silu gating + repack ----------------
// Thread = one channel d x 4 consecutive t. The 4 outputs share conv taps:
// for outputs t0..t0+3 only k[t0-6..t0] (7 values) are needed (taps at t-6+j, j=0..3).
// Same per-output fma order as before -> bit-identical results.
__global__ void gate_kernel(const float* __restrict__ conv_w, const float* __restrict__ conv_b) {
    int i = blockIdx.x * blockDim.x + threadIdx.x;
    if (i >= MMR * DD / 4) return;
    int d   = i & (DD - 1);
    int bt4 = i >> 10;
    int t0  = (bt4 & (TT/4 - 1)) * 4;
    int b   = bt4 >> 9;

    const float* kcol = g_proj + 2 * DD + d;
    const size_t rowstride = NPJ;
    const size_t base = (size_t)(b * TT) * rowstride;

    float kv[7];
#pragma unroll
    for (int u = 0; u < 7; ++u) {
        int tt = t0 - 6 + u;
        kv[u] = (tt >= 0) ? kcol[base + (size_t)tt * rowstride] : 0.f;
    }

    float4 cw = *(const float4*)(conv_w + d * 4);
    const float cwj[4] = {cw.x, cw.y, cw.z, cw.w};
    float cb = conv_b[d];

    int h = d >> 6, kk = d & 63;
    float* vout = g_vbuf + ((size_t)(b * HH + h) * TT) * KH + kk;
    const float* vcol = g_proj + DD + d;

#pragma unroll
    for (int q = 0; q < 4; ++q) {
        float ko = cb;
#pragma unroll
        for (int j = 0; j < 4; ++j)
            ko = fmaf(cwj[j], kv[q + j], ko);
        float sk = ko / (1.f + __expf(-ko));
        float v  = vcol[base + (size_t)(t0 + q) * rowstride];
        vout[(size_t)(t0 + q) * KH] = v * sk * SCALE_V;
    }
}

// ---------------- decay multiplier per (b,h,t) ----------------
__global__ void decay_kernel(const float* __restrict__ dp) {
    int idx = blockIdx.x * blockDim.x + threadIdx.x;
    if (idx >= BB * TT * HH) return;
    int h  = idx & (HH - 1);
    int bt = idx >> 4;
    float wv = g_proj[(size_t)bt * NPJ + 3 * DD + h];
    float gg = 1.f / (1.f + expf(-(dp[h] + wv)));
    float a  = expf(-8.f * (1.f - gg) - 0.1f);           // exp(log_decay), <= exp(-0.1)
    int b = bt >> 11, t = bt & (TT - 1);
    g_adec[(b * HH + h) * TT + t] = a;
}

// ---------------- chunked scan, 4-way unrolled, fused silu(r)*y + GN partials ----------------
__global__ void scan_kernel() {
    const int c  = blockIdx.x & (NCH - 1);
    const int bh = blockIdx.x >> 5;
    const int b  = bh >> 4, h = bh & (HH - 1);
    const int k  = threadIdx.x;                          // 0..63
    const int t0 = c * SCH;
    int s0 = t0 - SLB; if (s0 < 0) s0 = 0;
    const float* vp = g_vbuf + (size_t)bh * TT * KH;
    const float* ap = g_adec + (size_t)bh * TT;
    const int col = h * KH + k;

    float y = 0.f;
    for (int s = s0; s < t0; s += 4) {                   // lookback warm-up
        float4 a4 = *(const float4*)(ap + s);
        float v0 = vp[(size_t)(s + 0) * KH + k];
        float v1 = vp[(size_t)(s + 1) * KH + k];
        float v2 = vp[(size_t)(s + 2) * KH + k];
        float v3 = vp[(size_t)(s + 3) * KH + k];
        y = fmaf(a4.x, y, v0);
        y = fmaf(a4.y, y, v1);
        y = fmaf(a4.z, y, v2);
        y = fmaf(a4.w, y, v3);
    }

    float s1 = 0.f, s2 = 0.f;
    for (int sm = t0; sm < t0 + SCH; sm += 4) {
        float4 a4 = *(const float4*)(ap + sm);
        float aa[4] = {a4.x, a4.y, a4.z, a4.w};
        float vv[4], rr[4];
#pragma unroll
        for (int j = 0; j < 4; ++j) {
            vv[j] = vp[(size_t)(sm + j) * KH + k];
            rr[j] = g_proj[(size_t)(b * TT + sm + j) * NPJ + col];
        }
#pragma unroll
        for (int j = 0; j < 4; ++j) {
            y = fmaf(aa[j], y, vv[j]);
            float r  = rr[j];
            float sr = r / (1.f + __expf(-r));
            float gv = sr * y;
            g_gbuf[(size_t)(b * TT + sm + j) * DD + col] = gv;
            s1 += gv;
            s2 = fmaf(gv, gv, s2);
        }
    }

    __shared__ float rs1[64], rs2[64];
    rs1[k] = s1; rs2[k] = s2;
    __syncthreads();
    for (int off = 32; off > 0; off >>= 1) {
        if (k < off) { rs1[k] += rs1[k + off]; rs2[k] += rs2[k + off]; }
        __syncthreads();
    }
    if (k == 0) g_psum[bh * NCH + c] = make_float2(rs1[0], rs2[0]);
}

// ---------------- GroupNorm statistics (deterministic combine) ----------------
__global__ void stats_kernel() {
    int gi = threadIdx.x;
    if (gi >= BB * HH) return;
    float s1 = 0.f, s2 = 0.f;
    for (int c = 0; c < NCH; ++c) {
        float2 p = g_psum[gi * NCH + c];
        s1 += p.x; s2 += p.y;
    }
    const float inv = 1.f / (float)(KH * TT);
    float mean = s1 * inv;
    float var  = s2 * inv - mean * mean;
    g_stats[gi] = make_float2(mean, rsqrtf(var + 1e-5f));
}

// ---------------- normalize + affine + fp16 convert (x4) ----------------
__global__ void normcvt_kernel(const float* __restrict__ gn_w, const float* __restrict__ gn_b) {
    int i4 = blockIdx.x * blockDim.x + threadIdx.x;
    if (i4 >= MMR * DD / 4) return;
    int idx = i4 * 4;
    int d  = idx & (DD - 1);
    int bt = idx >> 10;
    int b  = bt >> 11;
    int h  = d >> 6;
    float2 st = g_stats[b * HH + h];
    float4 gv = *(const float4*)(g_gbuf + idx);
    float4 w4 = *(const float4*)(gn_w + d);
    float4 b4 = *(const float4*)(gn_b + d);
    __half2* ph = (__half2*)(g_gh + idx);
    ph[0] = __halves2half2(__float2half_rn(fmaf((gv.x - st.x) * st.y, w4.x, b4.x)),
                           __float2half_rn(fmaf((gv.y - st.x) * st.y, w4.y, b4.y)));
    ph[1] = __halves2half2(__float2half_rn(fmaf((gv.z - st.x) * st.y, w4.z, b4.z)),
                           __float2half_rn(fmaf((gv.w - st.x) * st.y, w4.w, b4.w)));
}

// ---------------- launch ----------------
extern "C" void kernel_launch(void* const* d_in, const int* in_sizes, int n_in,
                              void* d_out, int out_size) {
    const float* x      = (const float*)d_in[0];
    const float* W_in   = (const float*)d_in[1];
    const float* conv_w = (const float*)d_in[2];
    const float* conv_b = (const float*)d_in[3];
    const float* dp     = (const float*)d_in[4];
    const float* gn_w   = (const float*)d_in[5];
    const float* gn_b   = (const float*)d_in[6];
    const float* W_out  = (const float*)d_in[7];
    float* out = (float*)d_out;
    (void)in_sizes; (void)n_in; (void)out_size;

    void *pxh, *pwih, *pwoh, *pproj, *pgh;
    cudaGetSymbolAddress(&pxh,  g_xh);
    cudaGetSymbolAddress(&pwih, g_wih);
    cudaGetSymbolAddress(&pwoh, g_woh);
    cudaGetSymbolAddress(&pproj, g_proj);
    cudaGetSymbolAddress(&pgh,  g_gh);

    cudaFuncSetAttribute(gemm1p_kernel,
                         cudaFuncAttributeMaxDynamicSharedMemorySize, GSMEM);

    const int TPB = 256;
    cvt_kernel<<<(MMR*DD/4 + TPB-1)/TPB, TPB>>>((const float4*)x,     (__half2*)pxh,  MMR*DD/4);
    cvt_kernel<<<(NPJ*DD/4 + TPB-1)/TPB, TPB>>>((const float4*)W_in,  (__half2*)pwih, NPJ*DD/4);
    cvt_kernel<<<(DD*DD/4  + TPB-1)/TPB, TPB>>>((const float4*)W_out, (__half2*)pwoh, DD*DD/4);

    // GEMM1: proj = x @ W_in^T (single-pass fp16, fp32 accum)
    dim3 gg1((NPJ + BN - 1)/BN, MMR/BM);
    gemm1p_kernel<<<gg1, 256, GSMEM>>>((__half*)pxh, (__half*)pwih,
                                       (float*)pproj, MMR, NPJ, DD);

    gate_kernel <<<(MMR*DD/4 + TPB-1)/TPB, TPB>>>(conv_w, conv_b);
    decay_kernel<<<(BB*TT*HH + TPB-1)/TPB, TPB>>>(dp);
    scan_kernel <<<BB*HH*NCH, 64>>>();
    stats_kernel<<<1, 32>>>();
    normcvt_kernel<<<(MMR*DD/4 + TPB-1)/TPB, TPB>>>(gn_w, gn_b);

    // GEMM2: out = g_norm @ W_out^T
    dim3 gg2(DD/BN, MMR/BM);
    gemm1p_kernel<<<gg2, 256, GSMEM>>>((__half*)pgh, (__half*)pwoh,
                                       out, MMR, DD, DD);
}

// round 13
// speedup vs baseline: 1.1434x; 1.0035x over previous
#include <cuda_runtime.h>
#include <cuda_fp16.h>
#include <cstdint>
#include <cstddef>

// ---------------- problem constants ----------------
#define BB   2
#define TT   2048
#define DD   1024
#define HH   16
#define KH   64          // D / H
#define NPJ  3088        // 3*D + H
#define MMR  4096        // B*T
#define SCALE_V 0.03125f // 1/sqrt(D)
#define SCH  64          // scan chunk
#define SLB  128         // scan lookback (err <= e^-12.8 ~ 2.7e-6)
#define NCH  (TT/SCH)    // 32

// ---------------- scratch (__device__ globals; no allocations) ----------------
__device__ __half g_xh [MMR*DD];
__device__ __half g_wih[NPJ*DD];
__device__ __half g_woh[DD*DD];
__device__ float  g_proj[(size_t)MMR*NPJ]; // (B*T, 3D+H)
__device__ float  g_vbuf[MMR*DD];          // (B,H,T,K) gated v * scale
__device__ float  g_adec[BB*HH*TT];        // (B,H,T) decay multiplier
__device__ float  g_gbuf[MMR*DD];          // (B,T,D) silu(r)*y
__device__ __half g_gh [MMR*DD];
__device__ float2 g_psum[BB*HH*NCH];       // partial (sum, sumsq) per group-chunk
__device__ float2 g_stats[BB*HH];          // (mean, rstd)

// ---------------- fp32 -> fp16 (float4 vectorized) ----------------
__global__ void cvt_kernel(const float4* __restrict__ in, __half2* __restrict__ hi, int n4) {
    int i = blockIdx.x * blockDim.x + threadIdx.x;
    if (i >= n4) return;
    float4 v = in[i];
    hi[2*i]   = __halves2half2(__float2half_rn(v.x), __float2half_rn(v.y));
    hi[2*i+1] = __halves2half2(__float2half_rn(v.z), __float2half_rn(v.w));
}

// ---------------- single-pass fp16 GEMM: C = A*B^T (fp32 accum) ----------------
// 128x128 CTA tile, 256 threads, 4x2 warps of 32x64.
// Pair-unrolled mainloop: 2 k-chunks per iteration, ONE __syncthreads per pair.
#define BM 128
#define BN 128
#define BK 32
#define AST 40                       // padded smem row stride in halves
#define NSTG 4                       // chunk buffers
#define STGA (BM*AST*2)              // 10240 bytes per A stage
#define STGB (BN*AST*2)              // 10240 bytes per B stage
#define STG  (STGA+STGB)             // 20480 bytes per stage
#define GSMEM (NSTG*STG)             // 81920 bytes dynamic smem

__device__ __forceinline__ void ldsm4(uint32_t& r0, uint32_t& r1, uint32_t& r2, uint32_t& r3,
                                      uint32_t addr) {
    asm volatile("ldmatrix.sync.aligned.m8n8.x4.shared.b16 {%0,%1,%2,%3}, [%4];"
                 : "=r"(r0), "=r"(r1), "=r"(r2), "=r"(r3) : "r"(addr));
}

extern __shared__ char gsm[];

__global__ void __launch_bounds__(256, 2) gemm1p_kernel(
    const __half* __restrict__ A, const __half* __restrict__ B,
    float* __restrict__ C, int M, int N, int K)
{
    const uint32_t sbase = (uint32_t)__cvta_generic_to_shared(gsm);

    const int tid  = threadIdx.x;
    const int warp = tid >> 5, lane = tid & 31;
    const int wm = warp & 3, wn = warp >> 2;      // 4 x 2 warp grid
    const int g  = lane >> 2, tg = lane & 3;
    const int bm = blockIdx.y * BM;
    const int bn = blockIdx.x * BN;
    const int KT = K / BK;                        // k-chunks (even: K=1024 -> 32)
    const int lr = tid >> 2;          // 0..63
    const int lc = (tid & 3) * 8;     // 0,8,16,24 halves

    const uint32_t dA0 = (lr * AST + lc) * 2;
    const uint32_t dA1 = ((lr + 64) * AST + lc) * 2;

    const int n0 = bn + lr, n1 = bn + lr + 64;
    const int p0 = (n0 < N) ? 16 : 0;
    const int p1 = (n1 < N) ? 16 : 0;
    const size_t aoff0 = (size_t)(bm + lr) * K + lc;
    const size_t aoff1 = (size_t)(bm + lr + 64) * K + lc;
    const size_t boff0 = (size_t)((n0 < N) ? n0 : N - 1) * K + lc;
    const size_t boff1 = (size_t)((n1 < N) ? n1 : N - 1) * K + lc;

    auto ISSUE = [&](int chunk) {
        int kk = chunk * BK;
        uint32_t st = sbase + (chunk & (NSTG - 1)) * STG;
        asm volatile("cp.async.cg.shared.global [%0], [%1], 16;\n"
                     :: "r"(st + dA0), "l"(A + aoff0 + kk));
        asm volatile("cp.async.cg.shared.global [%0], [%1], 16;\n"
                     :: "r"(st + dA1), "l"(A + aoff1 + kk));
        asm volatile("cp.async.cg.shared.global [%0], [%1], 16, %2;\n"
                     :: "r"(st + STGA + dA0), "l"(B + boff0 + kk), "r"(p0));
        asm volatile("cp.async.cg.shared.global [%0], [%1], 16, %2;\n"
                     :: "r"(st + STGA + dA1), "l"(B + boff1 + kk), "r"(p1));
        asm volatile("cp.async.commit_group;\n");
    };

    float acc[2][8][4];
#pragma unroll
    for (int i = 0; i < 2; i++)
#pragma unroll
        for (int j = 0; j < 8; j++)
#pragma unroll
            for (int q = 0; q < 4; q++) acc[i][j][q] = 0.f;

    // ldmatrix per-lane address components
    const uint32_t a_row = wm * 32 + (lane & 15);
    const uint32_t a_ko  = (lane >> 4) << 3;
    const uint32_t b_row = wn * 64 + (lane & 7) + ((lane & 16) >> 1);
    const uint32_t b_ko  = (lane & 8);

    // pipeline: pre-issue pair {0,1}; per iter: wait pair, 1 barrier,
    // issue pair {it+2,it+3} (bufs of it-2/it-1, drained by the barrier),
    // then compute chunks it and it+1 back-to-back.
    ISSUE(0); ISSUE(1);

    for (int it = 0; it < KT; it += 2) {
        asm volatile("cp.async.wait_group 0;\n" ::: "memory");
        __syncthreads();
        if (it + 2 < KT) { ISSUE(it + 2); ISSUE(it + 3); }

#pragma unroll
        for (int half = 0; half < 2; ++half) {
            const uint32_t st = sbase + ((it + half) & (NSTG - 1)) * STG;
            const uint32_t Ab = st;
            const uint32_t Bb = st + STGA;
#pragma unroll
            for (int ks = 0; ks < 2; ++ks) {
                uint32_t ra[2][4];
#pragma unroll
                for (int mi = 0; mi < 2; ++mi) {
                    uint32_t addr = Ab + ((a_row + mi * 16) * AST + ks * 16 + a_ko) * 2;
                    ldsm4(ra[mi][0], ra[mi][1], ra[mi][2], ra[mi][3], addr);
                }
                uint32_t rb[8][2];
#pragma unroll
                for (int ni2 = 0; ni2 < 4; ++ni2) {
                    uint32_t addr = Bb + ((b_row + ni2 * 16) * AST + ks * 16 + b_ko) * 2;
                    ldsm4(rb[2*ni2][0], rb[2*ni2][1], rb[2*ni2+1][0], rb[2*ni2+1][1], addr);
                }
#pragma unroll
                for (int mi = 0; mi < 2; ++mi)
#pragma unroll
                    for (int ni = 0; ni < 8; ++ni)
                        asm volatile(
                            "mma.sync.aligned.m16n8k16.row.col.f32.f16.f16.f32 "
                            "{%0,%1,%2,%3},{%4,%5,%6,%7},{%8,%9},{%0,%1,%2,%3};\n"
                            : "+f"(acc[mi][ni][0]), "+f"(acc[mi][ni][1]),
                              "+f"(acc[mi][ni][2]), "+f"(acc[mi][ni][3])
                            : "r"(ra[mi][0]), "r"(ra[mi][1]), "r"(ra[mi][2]), "r"(ra[mi][3]),
                              "r"(rb[ni][0]), "r"(rb[ni][1]));
            }
        }
    }

#pragma unroll
    for (int mi = 0; mi < 2; ++mi) {
        int r0 = bm + wm * 32 + mi * 16 + g;
#pragma unroll
        for (int ni = 0; ni < 8; ++ni) {
            int c0 = bn + wn * 64 + ni * 8 + tg * 2;
            if (c0 < N) {
                *(float2*)(C + (size_t)r0       * N + c0) = make_float2(acc[mi][ni][0], acc[mi][ni][1]);
                *(float2*)(C + (size_t)(r0 + 8) * N + c0) = make_float2(acc[mi][ni][2], acc[mi][ni][3]);
            }
        }
    }
}

// ---------------- gate: shifted depthwise conv + silu gating + repack ----------------
// Thread = one channel d x 4 consecutive t; 4 outputs share the 7 needed k-taps.
__global__ void gate_kernel(const float* __restrict__ conv_w, const float* __restrict__ conv_b) {
    int i = blockIdx.x * blockDim.x + threadIdx.x;
    if (i >= MMR * DD / 4) return;
    int d   = i & (DD - 1);
    int bt4 = i >> 10;
    int t0  = (bt4 & (TT/4 - 1)) * 4;
    int b   = bt4 >> 9;

    const float* kcol = g_proj + 2 * DD + d;
    const size_t rowstride = NPJ;
    const size_t base = (size_t)(b * TT) * rowstride;

    float kv[7];
#pragma unroll
    for (int u = 0; u < 7; ++u) {
        int tt = t0 - 6 + u;
        kv[u] = (tt >= 0) ? kcol[base + (size_t)tt * rowstride] : 0.f;
    }

    float4 cw = *(const float4*)(conv_w + d * 4);
    const float cwj[4] = {cw.x, cw.y, cw.z, cw.w};
    float cb = conv_b[d];

    int h = d >> 6, kk = d & 63;
    float* vout = g_vbuf + ((size_t)(b * HH + h) * TT) * KH + kk;
    const float* vcol = g_proj + DD + d;

#pragma unroll
    for (int q = 0; q < 4; ++q) {
        float ko = cb;
#pragma unroll
        for (int j = 0; j < 4; ++j)
            ko = fmaf(cwj[j], kv[q + j], ko);
        float sk = ko / (1.f + __expf(-ko));
        float v  = vcol[base + (size_t)(t0 + q) * rowstride];
        vout[(size_t)(t0 + q) * KH] = v * sk * SCALE_V;
    }
}

// ---------------- decay multiplier per (b,h,t) ----------------
__global__ void decay_kernel(const float* __restrict__ dp) {
    int idx = blockIdx.x * blockDim.x + threadIdx.x;
    if (idx >= BB * TT * HH) return;
    int h  = idx & (HH - 1);
    int bt = idx >> 4;
    float wv = g_proj[(size_t)bt * NPJ + 3 * DD + h];
    float gg = 1.f / (1.f + expf(-(dp[h] + wv)));
    float a  = expf(-8.f * (1.f - gg) - 0.1f);           // exp(log_decay), <= exp(-0.1)
    int b = bt >> 11, t = bt & (TT - 1);
    g_adec[(b * HH + h) * TT + t] = a;
}

// ---------------- chunked scan, 4-way unrolled, fused silu(r)*y + GN partials ----------------
__global__ void scan_kernel() {
    const int c  = blockIdx.x & (NCH - 1);
    const int bh = blockIdx.x >> 5;
    const int b  = bh >> 4, h = bh & (HH - 1);
    const int k  = threadIdx.x;                          // 0..63
    const int t0 = c * SCH;
    int s0 = t0 - SLB; if (s0 < 0) s0 = 0;
    const float* vp = g_vbuf + (size_t)bh * TT * KH;
    const float* ap = g_adec + (size_t)bh * TT;
    const int col = h * KH + k;

    float y = 0.f;
    for (int s = s0; s < t0; s += 4) {                   // lookback warm-up
        float4 a4 = *(const float4*)(ap + s);
        float v0 = vp[(size_t)(s + 0) * KH + k];
        float v1 = vp[(size_t)(s + 1) * KH + k];
        float v2 = vp[(size_t)(s + 2) * KH + k];
        float v3 = vp[(size_t)(s + 3) * KH + k];
        y = fmaf(a4.x, y, v0);
        y = fmaf(a4.y, y, v1);
        y = fmaf(a4.z, y, v2);
        y = fmaf(a4.w, y, v3);
    }

    float s1 = 0.f, s2 = 0.f;
    for (int sm = t0; sm < t0 + SCH; sm += 4) {
        float4 a4 = *(const float4*)(ap + sm);
        float aa[4] = {a4.x, a4.y, a4.z, a4.w};
        float vv[4], rr[4];
#pragma unroll
        for (int j = 0; j < 4; ++j) {
            vv[j] = vp[(size_t)(sm + j) * KH + k];
            rr[j] = g_proj[(size_t)(b * TT + sm + j) * NPJ + col];
        }
#pragma unroll
        for (int j = 0; j < 4; ++j) {
            y = fmaf(aa[j], y, vv[j]);
            float r  = rr[j];
            float sr = r / (1.f + __expf(-r));
            float gv = sr * y;
            g_gbuf[(size_t)(b * TT + sm + j) * DD + col] = gv;
            s1 += gv;
            s2 = fmaf(gv, gv, s2);
        }
    }

    __shared__ float rs1[64], rs2[64];
    rs1[k] = s1; rs2[k] = s2;
    __syncthreads();
    for (int off = 32; off > 0; off >>= 1) {
        if (k < off) { rs1[k] += rs1[k + off]; rs2[k] += rs2[k + off]; }
        __syncthreads();
    }
    if (k == 0) g_psum[bh * NCH + c] = make_float2(rs1[0], rs2[0]);
}

// ---------------- GroupNorm statistics (deterministic combine) ----------------
__global__ void stats_kernel() {
    int gi = threadIdx.x;
    if (gi >= BB * HH) return;
    float s1 = 0.f, s2 = 0.f;
    for (int c = 0; c < NCH; ++c) {
        float2 p = g_psum[gi * NCH + c];
        s1 += p.x; s2 += p.y;
    }
    const float inv = 1.f / (float)(KH * TT);
    float mean = s1 * inv;
    float var  = s2 * inv - mean * mean;
    g_stats[gi] = make_float2(mean, rsqrtf(var + 1e-5f));
}

// ---------------- normalize + affine + fp16 convert (x4) ----------------
__global__ void normcvt_kernel(const float* __restrict__ gn_w, const float* __restrict__ gn_b) {
    int i4 = blockIdx.x * blockDim.x + threadIdx.x;
    if (i4 >= MMR * DD / 4) return;
    int idx = i4 * 4;
    int d  = idx & (DD - 1);
    int bt = idx >> 10;
    int b  = bt >> 11;
    int h  = d >> 6;
    float2 st = g_stats[b * HH + h];
    float4 gv = *(const float4*)(g_gbuf + idx);
    float4 w4 = *(const float4*)(gn_w + d);
    float4 b4 = *(const float4*)(gn_b + d);
    __half2* ph = (__half2*)(g_gh + idx);
    ph[0] = __halves2half2(__float2half_rn(fmaf((gv.x - st.x) * st.y, w4.x, b4.x)),
                           __float2half_rn(fmaf((gv.y - st.x) * st.y, w4.y, b4.y)));
    ph[1] = __halves2half2(__float2half_rn(fmaf((gv.z - st.x) * st.y, w4.z, b4.z)),
                           __float2half_rn(fmaf((gv.w - st.x) * st.y, w4.w, b4.w)));
}

// ---------------- launch ----------------
extern "C" void kernel_launch(void* const* d_in, const int* in_sizes, int n_in,
                              void* d_out, int out_size) {
    const float* x      = (const float*)d_in[0];
    const float* W_in   = (const float*)d_in[1];
    const float* conv_w = (const float*)d_in[2];
    const float* conv_b = (const float*)d_in[3];
    const float* dp     = (const float*)d_in[4];
    const float* gn_w   = (const float*)d_in[5];
    const float* gn_b   = (const float*)d_in[6];
    const float* W_out  = (const float*)d_in[7];
    float* out = (float*)d_out;
    (void)in_sizes; (void)n_in; (void)out_size;

    void *pxh, *pwih, *pwoh, *pproj, *pgh;
    cudaGetSymbolAddress(&pxh,  g_xh);
    cudaGetSymbolAddress(&pwih, g_wih);
    cudaGetSymbolAddress(&pwoh, g_woh);
    cudaGetSymbolAddress(&pproj, g_proj);
    cudaGetSymbolAddress(&pgh,  g_gh);

    cudaFuncSetAttribute(gemm1p_kernel,
                         cudaFuncAttributeMaxDynamicSharedMemorySize, GSMEM);

    const int TPB = 256;
    cvt_kernel<<<(MMR*DD/4 + TPB-1)/TPB, TPB>>>((const float4*)x,     (__half2*)pxh,  MMR*DD/4);
    cvt_kernel<<<(NPJ*DD/4 + TPB-1)/TPB, TPB>>>((const float4*)W_in,  (__half2*)pwih, NPJ*DD/4);
    cvt_kernel<<<(DD*DD/4  + TPB-1)/TPB, TPB>>>((const float4*)W_out, (__half2*)pwoh, DD*DD/4);

    // GEMM1: proj = x @ W_in^T (single-pass fp16, fp32 accum)
    dim3 gg1((NPJ + BN - 1)/BN, MMR/BM);
    gemm1p_kernel<<<gg1, 256, GSMEM>>>((__half*)pxh, (__half*)pwih,
                                       (float*)pproj, MMR, NPJ, DD);

    gate_kernel <<<(MMR*DD/4 + TPB-1)/TPB, TPB>>>(conv_w, conv_b);
    decay_kernel<<<(BB*TT*HH + TPB-1)/TPB, TPB>>>(dp);
    scan_kernel <<<BB*HH*NCH, 64>>>();
    stats_kernel<<<1, 32>>>();
    normcvt_kernel<<<(MMR*DD/4 + TPB-1)/TPB, TPB>>>(gn_w, gn_b);

    // GEMM2: out = g_norm @ W_out^T
    dim3 gg2(DD/BN, MMR/BM);
    gemm1p_kernel<<<gg2, 256, GSMEM>>>((__half*)pgh, (__half*)pwoh,
                                       out, MMR, DD, DD);
}

// round 15
// speedup vs baseline: 1.1949x; 1.0450x over previous
#include <cuda_runtime.h>
#include <cuda_fp16.h>
#include <cstdint>
#include <cstddef>

// ---------------- problem constants ----------------
#define BB   2
#define TT   2048
#define DD   1024
#define HH   16
#define KH   64          // D / H
#define NPJ  3088        // 3*D + H
#define MMR  4096        // B*T
#define SCALE_V 0.03125f // 1/sqrt(D)
#define SCH  64          // scan chunk
#define SLB  128         // scan lookback (err <= e^-12.8 ~ 2.7e-6)
#define NCH  (TT/SCH)    // 32

// ---------------- scratch (__device__ globals; no allocations) ----------------
__device__ __half g_xh [MMR*DD];
__device__ __half g_wih[NPJ*DD];
__device__ __half g_woh[DD*DD];
__device__ float  g_proj[(size_t)MMR*NPJ]; // (B*T, 3D+H)
__device__ float  g_vbuf[MMR*DD];          // (B,H,T,K) gated v * scale
__device__ float  g_adec[BB*HH*TT];        // (B,H,T) decay multiplier
__device__ float  g_gbuf[MMR*DD];          // (B,T,D) silu(r)*y
__device__ __half g_gh [MMR*DD];
__device__ float2 g_psum[BB*HH*NCH];       // partial (sum, sumsq) per group-chunk
__device__ float2 g_stats[BB*HH];          // (mean, rstd)

// ---------------- fp32 -> fp16 (float4 vectorized) ----------------
__global__ void cvt_kernel(const float4* __restrict__ in, __half2* __restrict__ hi, int n4) {
    int i = blockIdx.x * blockDim.x + threadIdx.x;
    if (i >= n4) return;
    float4 v = in[i];
    hi[2*i]   = __halves2half2(__float2half_rn(v.x), __float2half_rn(v.y));
    hi[2*i+1] = __halves2half2(__float2half_rn(v.z), __float2half_rn(v.w));
}

// ---------------- single-pass fp16 GEMM: C = A*B^T (fp32 accum) ----------------
// 128x128 CTA tile, 256 threads, 4x2 warps of 32x64.
// Barrier-certified deep pipeline (issue-ahead 4): at each end-of-iter barrier,
// chunks <= it+2 are complete for ALL threads, so both fragment prefetches of
// the next iteration read only certified stages -- no intra-iteration waits,
// and LDSM (smem pipe) overlaps the HMMA bursts (tensor pipe).
#define BM 128
#define BN 128
#define BK 32
#define AST 40                       // padded smem row stride in halves
#define NSTG 4                       // chunk buffers
#define STGA (BM*AST*2)              // 10240 bytes per A stage
#define STGB (BN*AST*2)              // 10240 bytes per B stage
#define STG  (STGA+STGB)             // 20480 bytes per stage
#define GSMEM (NSTG*STG)             // 81920 bytes dynamic smem

__device__ __forceinline__ void ldsm4(uint32_t& r0, uint32_t& r1, uint32_t& r2, uint32_t& r3,
                                      uint32_t addr) {
    asm volatile("ldmatrix.sync.aligned.m8n8.x4.shared.b16 {%0,%1,%2,%3}, [%4];"
                 : "=r"(r0), "=r"(r1), "=r"(r2), "=r"(r3) : "r"(addr));
}

extern __shared__ char gsm[];

__global__ void __launch_bounds__(256, 2) gemm1p_kernel(
    const __half* __restrict__ A, const __half* __restrict__ B,
    float* __restrict__ C, int M, int N, int K)
{
    const uint32_t sbase = (uint32_t)__cvta_generic_to_shared(gsm);

    const int tid  = threadIdx.x;
    const int warp = tid >> 5, lane = tid & 31;
    const int wm = warp & 3, wn = warp >> 2;      // 4 x 2 warp grid
    const int g  = lane >> 2, tg = lane & 3;
    const int bm = blockIdx.y * BM;
    const int bn = blockIdx.x * BN;
    const int KT = K / BK;                        // k-chunks (K=1024 -> 32)
    const int lr = tid >> 2;          // 0..63
    const int lc = (tid & 3) * 8;     // 0,8,16,24 halves

    const uint32_t dA0 = (lr * AST + lc) * 2;
    const uint32_t dA1 = ((lr + 64) * AST + lc) * 2;

    const int n0 = bn + lr, n1 = bn + lr + 64;
    const int p0 = (n0 < N) ? 16 : 0;
    const int p1 = (n1 < N) ? 16 : 0;
    // 32-bit element offsets (max ~8.4M elements, fits easily)
    const __half* pA0 = A + (uint32_t)(bm + lr) * (uint32_t)K + lc;
    const __half* pA1 = A + (uint32_t)(bm + lr + 64) * (uint32_t)K + lc;
    const __half* pB0 = B + (uint32_t)((n0 < N) ? n0 : N - 1) * (uint32_t)K + lc;
    const __half* pB1 = B + (uint32_t)((n1 < N) ? n1 : N - 1) * (uint32_t)K + lc;

    auto ISSUE = [&](int chunk) {
        int kk = chunk * BK;
        uint32_t st = sbase + (chunk & (NSTG - 1)) * STG;
        asm volatile("cp.async.cg.shared.global [%0], [%1], 16;\n"
                     :: "r"(st + dA0), "l"(pA0 + kk));
        asm volatile("cp.async.cg.shared.global [%0], [%1], 16;\n"
                     :: "r"(st + dA1), "l"(pA1 + kk));
        asm volatile("cp.async.cg.shared.global [%0], [%1], 16, %2;\n"
                     :: "r"(st + STGA + dA0), "l"(pB0 + kk), "r"(p0));
        asm volatile("cp.async.cg.shared.global [%0], [%1], 16, %2;\n"
                     :: "r"(st + STGA + dA1), "l"(pB1 + kk), "r"(p1));
        asm volatile("cp.async.commit_group;\n");
    };

    float acc[2][8][4];
#pragma unroll
    for (int i = 0; i < 2; i++)
#pragma unroll
        for (int j = 0; j < 8; j++)
#pragma unroll
            for (int q = 0; q < 4; q++) acc[i][j][q] = 0.f;

    // ldmatrix per-lane address components
    const uint32_t a_row = wm * 32 + (lane & 15);
    const uint32_t a_ko  = (lane >> 4) << 3;
    const uint32_t b_row = wn * 64 + (lane & 7) + ((lane & 16) >> 1);
    const uint32_t b_ko  = (lane & 8);

    // two fragment buffers: ks0 -> frag0, ks1 -> frag1
    uint32_t ra0[2][4], ra1[2][4];
    uint32_t rb0[8][2], rb1[8][2];

    auto LOADA = [&](uint32_t (&r)[2][4], uint32_t Ab, int ks) {
#pragma unroll
        for (int mi = 0; mi < 2; ++mi) {
            uint32_t addr = Ab + ((a_row + mi * 16) * AST + ks * 16 + a_ko) * 2;
            ldsm4(r[mi][0], r[mi][1], r[mi][2], r[mi][3], addr);
        }
    };
    auto LOADB = [&](uint32_t (&r)[8][2], uint32_t Bb, int ks) {
#pragma unroll
        for (int ni2 = 0; ni2 < 4; ++ni2) {
            uint32_t addr = Bb + ((b_row + ni2 * 16) * AST + ks * 16 + b_ko) * 2;
            ldsm4(r[2*ni2][0], r[2*ni2][1], r[2*ni2+1][0], r[2*ni2+1][1], addr);
        }
    };
    auto MMA = [&](uint32_t (&rra)[2][4], uint32_t (&rrb)[8][2]) {
#pragma unroll
        for (int mi = 0; mi < 2; ++mi)
#pragma unroll
            for (int ni = 0; ni < 8; ++ni)
                asm volatile(
                    "mma.sync.aligned.m16n8k16.row.col.f32.f16.f16.f32 "
                    "{%0,%1,%2,%3},{%4,%5,%6,%7},{%8,%9},{%0,%1,%2,%3};\n"
                    : "+f"(acc[mi][ni][0]), "+f"(acc[mi][ni][1]),
                      "+f"(acc[mi][ni][2]), "+f"(acc[mi][ni][3])
                    : "r"(rra[mi][0]), "r"(rra[mi][1]), "r"(rra[mi][2]), "r"(rra[mi][3]),
                      "r"(rrb[ni][0]), "r"(rrb[ni][1]));
    };

    // prologue: 4 groups in flight; certify chunks 0,1 for all threads
    ISSUE(0); ISSUE(1); ISSUE(2); ISSUE(3);
    asm volatile("cp.async.wait_group 2;\n" ::: "memory");
    __syncthreads();
    LOADA(ra0, sbase, 0);
    LOADB(rb0, sbase + STGA, 0);

    for (int it = 0; it < KT; ++it) {
        const uint32_t st = sbase + (it & (NSTG - 1)) * STG;

        // frag1 <- (it, ks1): stage certified at last barrier. HMMA frag0 overlaps.
        LOADA(ra1, st, 1);
        LOADB(rb1, st + STGA, 1);
        MMA(ra0, rb0);

        // frag0 <- (it+1, ks0): also certified at last barrier. Overlaps frag1 HMMA.
        if (it + 1 < KT) {
            const uint32_t stn = sbase + ((it + 1) & (NSTG - 1)) * STG;
            LOADA(ra0, stn, 0);
            LOADB(rb0, stn + STGA, 0);
        }
        MMA(ra1, rb1);

        // certify chunks <= it+2 for all threads, then refill one stage
        if (it + 3 >= KT) asm volatile("cp.async.wait_group 0;\n" ::: "memory");
        else              asm volatile("cp.async.wait_group 1;\n" ::: "memory");
        __syncthreads();
        if (it + 4 < KT) ISSUE(it + 4);   // overwrites stage it&3: last read pre-barrier
    }

#pragma unroll
    for (int mi = 0; mi < 2; ++mi) {
        int r0 = bm + wm * 32 + mi * 16 + g;
#pragma unroll
        for (int ni = 0; ni < 8; ++ni) {
            int c0 = bn + wn * 64 + ni * 8 + tg * 2;
            if (c0 < N) {
                *(float2*)(C + (size_t)r0       * N + c0) = make_float2(acc[mi][ni][0], acc[mi][ni][1]);
                *(float2*)(C + (size_t)(r0 + 8) * N + c0) = make_float2(acc[mi][ni][2], acc[mi][ni][3]);
            }
        }
    }
}

// ---------------- gate: shifted depthwise conv + silu gating + repack ----------------
// Thread = one channel d x 4 consecutive t; 4 outputs share the 7 needed k-taps.
__global__ void gate_kernel(const float* __restrict__ conv_w, const float* __restrict__ conv_b) {
    int i = blockIdx.x * blockDim.x + threadIdx.x;
    if (i >= MMR * DD / 4) return;
    int d   = i & (DD - 1);
    int bt4 = i >> 10;
    int t0  = (bt4 & (TT/4 - 1)) * 4;
    int b   = bt4 >> 9;

    const float* kcol = g_proj + 2 * DD + d;
    const size_t rowstride = NPJ;
    const size_t base = (size_t)(b * TT) * rowstride;

    float kv[7];
#pragma unroll
    for (int u = 0; u < 7; ++u) {
        int tt = t0 - 6 + u;
        kv[u] = (tt >= 0) ? kcol[base + (size_t)tt * rowstride] : 0.f;
    }

    float4 cw = *(const float4*)(conv_w + d * 4);
    const float cwj[4] = {cw.x, cw.y, cw.z, cw.w};
    float cb = conv_b[d];

    int h = d >> 6, kk = d & 63;
    float* vout = g_vbuf + ((size_t)(b * HH + h) * TT) * KH + kk;
    const float* vcol = g_proj + DD + d;

#pragma unroll
    for (int q = 0; q < 4; ++q) {
        float ko = cb;
#pragma unroll
        for (int j = 0; j < 4; ++j)
            ko = fmaf(cwj[j], kv[q + j], ko);
        float sk = ko / (1.f + __expf(-ko));
        float v  = vcol[base + (size_t)(t0 + q) * rowstride];
        vout[(size_t)(t0 + q) * KH] = v * sk * SCALE_V;
    }
}

// ---------------- decay multiplier per (b,h,t) ----------------
__global__ void decay_kernel(const float* __restrict__ dp) {
    int idx = blockIdx.x * blockDim.x + threadIdx.x;
    if (idx >= BB * TT * HH) return;
    int h  = idx & (HH - 1);
    int bt = idx >> 4;
    float wv = g_proj[(size_t)bt * NPJ + 3 * DD + h];
    float gg = 1.f / (1.f + expf(-(dp[h] + wv)));
    float a  = expf(-8.f * (1.f - gg) - 0.1f);           // exp(log_decay), <= exp(-0.1)
    int b = bt >> 11, t = bt & (TT - 1);
    g_adec[(b * HH + h) * TT + t] = a;
}

// ---------------- chunked scan, 4-way unrolled, fused silu(r)*y + GN partials ----------------
__global__ void scan_kernel() {
    const int c  = blockIdx.x & (NCH - 1);
    const int bh = blockIdx.x >> 5;
    const int b  = bh >> 4, h = bh & (HH - 1);
    const int k  = threadIdx.x;                          // 0..63
    const int t0 = c * SCH;
    int s0 = t0 - SLB; if (s0 < 0) s0 = 0;
    const float* vp = g_vbuf + (size_t)bh * TT * KH;
    const float* ap = g_adec + (size_t)bh * TT;
    const int col = h * KH + k;

    float y = 0.f;
    for (int s = s0; s < t0; s += 4) {                   // lookback warm-up
        float4 a4 = *(const float4*)(ap + s);
        float v0 = vp[(size_t)(s + 0) * KH + k];
        float v1 = vp[(size_t)(s + 1) * KH + k];
        float v2 = vp[(size_t)(s + 2) * KH + k];
        float v3 = vp[(size_t)(s + 3) * KH + k];
        y = fmaf(a4.x, y, v0);
        y = fmaf(a4.y, y, v1);
        y = fmaf(a4.z, y, v2);
        y = fmaf(a4.w, y, v3);
    }

    float s1 = 0.f, s2 = 0.f;
    for (int sm = t0; sm < t0 + SCH; sm += 4) {
        float4 a4 = *(const float4*)(ap + sm);
        float aa[4] = {a4.x, a4.y, a4.z, a4.w};
        float vv[4], rr[4];
#pragma unroll
        for (int j = 0; j < 4; ++j) {
            vv[j] = vp[(size_t)(sm + j) * KH + k];
            rr[j] = g_proj[(size_t)(b * TT + sm + j) * NPJ + col];
        }
#pragma unroll
        for (int j = 0; j < 4; ++j) {
            y = fmaf(aa[j], y, vv[j]);
            float r  = rr[j];
            float sr = r / (1.f + __expf(-r));
            float gv = sr * y;
            g_gbuf[(size_t)(b * TT + sm + j) * DD + col] = gv;
            s1 += gv;
            s2 = fmaf(gv, gv, s2);
        }
    }

    __shared__ float rs1[64], rs2[64];
    rs1[k] = s1; rs2[k] = s2;
    __syncthreads();
    for (int off = 32; off > 0; off >>= 1) {
        if (k < off) { rs1[k] += rs1[k + off]; rs2[k] += rs2[k + off]; }
        __syncthreads();
    }
    if (k == 0) g_psum[bh * NCH + c] = make_float2(rs1[0], rs2[0]);
}

// ---------------- GroupNorm statistics (deterministic combine) ----------------
__global__ void stats_kernel() {
    int gi = threadIdx.x;
    if (gi >= BB * HH) return;
    float s1 = 0.f, s2 = 0.f;
    for (int c = 0; c < NCH; ++c) {
        float2 p = g_psum[gi * NCH + c];
        s1 += p.x; s2 += p.y;
    }
    const float inv = 1.f / (float)(KH * TT);
    float mean = s1 * inv;
    float var  = s2 * inv - mean * mean;
    g_stats[gi] = make_float2(mean, rsqrtf(var + 1e-5f));
}

// ---------------- normalize + affine + fp16 convert (x4) ----------------
__global__ void normcvt_kernel(const float* __restrict__ gn_w, const float* __restrict__ gn_b) {
    int i4 = blockIdx.x * blockDim.x + threadIdx.x;
    if (i4 >= MMR * DD / 4) return;
    int idx = i4 * 4;
    int d  = idx & (DD - 1);
    int bt = idx >> 10;
    int b  = bt >> 11;
    int h  = d >> 6;
    float2 st = g_stats[b * HH + h];
    float4 gv = *(const float4*)(g_gbuf + idx);
    float4 w4 = *(const float4*)(gn_w + d);
    float4 b4 = *(const float4*)(gn_b + d);
    __half2* ph = (__half2*)(g_gh + idx);
    ph[0] = __halves2half2(__float2half_rn(fmaf((gv.x - st.x) * st.y, w4.x, b4.x)),
                           __float2half_rn(fmaf((gv.y - st.x) * st.y, w4.y, b4.y)));
    ph[1] = __halves2half2(__float2half_rn(fmaf((gv.z - st.x) * st.y, w4.z, b4.z)),
                           __float2half_rn(fmaf((gv.w - st.x) * st.y, w4.w, b4.w)));
}

// ---------------- launch ----------------
extern "C" void kernel_launch(void* const* d_in, const int* in_sizes, int n_in,
                              void* d_out, int out_size) {
    const float* x      = (const float*)d_in[0];
    const float* W_in   = (const float*)d_in[1];
    const float* conv_w = (const float*)d_in[2];
    const float* conv_b = (const float*)d_in[3];
    const float* dp     = (const float*)d_in[4];
    const float* gn_w   = (const float*)d_in[5];
    const float* gn_b   = (const float*)d_in[6];
    const float* W_out  = (const float*)d_in[7];
    float* out = (float*)d_out;
    (void)in_sizes; (void)n_in; (void)out_size;

    void *pxh, *pwih, *pwoh, *pproj, *pgh;
    cudaGetSymbolAddress(&pxh,  g_xh);
    cudaGetSymbolAddress(&pwih, g_wih);
    cudaGetSymbolAddress(&pwoh, g_woh);
    cudaGetSymbolAddress(&pproj, g_proj);
    cudaGetSymbolAddress(&pgh,  g_gh);

    cudaFuncSetAttribute(gemm1p_kernel,
                         cudaFuncAttributeMaxDynamicSharedMemorySize, GSMEM);

    const int TPB = 256;
    cvt_kernel<<<(MMR*DD/4 + TPB-1)/TPB, TPB>>>((const float4*)x,     (__half2*)pxh,  MMR*DD/4);
    cvt_kernel<<<(NPJ*DD/4 + TPB-1)/TPB, TPB>>>((const float4*)W_in,  (__half2*)pwih, NPJ*DD/4);
    cvt_kernel<<<(DD*DD/4  + TPB-1)/TPB, TPB>>>((const float4*)W_out, (__half2*)pwoh, DD*DD/4);

    // GEMM1: proj = x @ W_in^T (single-pass fp16, fp32 accum)
    dim3 gg1((NPJ + BN - 1)/BN, MMR/BM);
    gemm1p_kernel<<<gg1, 256, GSMEM>>>((__half*)pxh, (__half*)pwih,
                                       (float*)pproj, MMR, NPJ, DD);

    gate_kernel <<<(MMR*DD/4 + TPB-1)/TPB, TPB>>>(conv_w, conv_b);
    decay_kernel<<<(BB*TT*HH + TPB-1)/TPB, TPB>>>(dp);
    scan_kernel <<<BB*HH*NCH, 64>>>();
    stats_kernel<<<1, 32>>>();
    normcvt_kernel<<<(MMR*DD/4 + TPB-1)/TPB, TPB>>>(gn_w, gn_b);

    // GEMM2: out = g_norm @ W_out^T
    dim3 gg2(DD/BN, MMR/BM);
    gemm1p_kernel<<<gg2, 256, GSMEM>>>((__half*)pgh, (__half*)pwoh,
                                       out, MMR, DD, DD);
}

// round 16
// speedup vs baseline: 1.2391x; 1.0370x over previous
#include <cuda_runtime.h>
#include <cuda_fp16.h>
#include <cstdint>
#include <cstddef>

// ---------------- problem constants ----------------
#define BB   2
#define TT   2048
#define DD   1024
#define HH   16
#define KH   64          // D / H
#define NPJ  3088        // 3*D + H
#define MMR  4096        // B*T
#define SCALE_V 0.03125f // 1/sqrt(D)
#define SCH  64          // scan chunk
#define SLB  128         // scan lookback (err <= e^-12.8 ~ 2.7e-6)
#define NCH  (TT/SCH)    // 32

// ---------------- scratch (__device__ globals; no allocations) ----------------
__device__ __half g_xh [MMR*DD];
__device__ __half g_wih[NPJ*DD];
__device__ __half g_woh[DD*DD];
__device__ float  g_proj[(size_t)MMR*NPJ]; // (B*T, 3D+H)
__device__ __half g_vbuf[MMR*DD];          // (B,H,T,K) gated v * scale (fp16)
__device__ float  g_adec[BB*HH*TT];        // (B,H,T) decay multiplier
__device__ __half g_gh [MMR*DD];           // g = silu(r)*y (fp16); normalized in place
__device__ float2 g_psum[BB*HH*NCH];       // partial (sum, sumsq) per group-chunk
__device__ float2 g_stats[BB*HH];          // (mean, rstd)

// ---------------- fused fp32 -> fp16 conversion for x, W_in, W_out ----------------
#define N4X (MMR*DD/4)
#define N4WI (NPJ*DD/4)
#define N4WO (DD*DD/4)
__global__ void cvt3_kernel(const float4* __restrict__ x,
                            const float4* __restrict__ wi,
                            const float4* __restrict__ wo) {
    int i = blockIdx.x * blockDim.x + threadIdx.x;
    const float4* src;
    __half2* dst;
    int j;
    if (i < N4X)                { src = x;  dst = (__half2*)g_xh;  j = i; }
    else if (i < N4X + N4WI)    { src = wi; dst = (__half2*)g_wih; j = i - N4X; }
    else if (i < N4X+N4WI+N4WO) { src = wo; dst = (__half2*)g_woh; j = i - N4X - N4WI; }
    else return;
    float4 v = src[j];
    dst[2*j]   = __halves2half2(__float2half_rn(v.x), __float2half_rn(v.y));
    dst[2*j+1] = __halves2half2(__float2half_rn(v.z), __float2half_rn(v.w));
}

// ---------------- single-pass fp16 GEMM: C = A*B^T (fp32 accum) ----------------
// 128x128 CTA tile, 256 threads, 4x2 warps of 32x64.
// Barrier-certified deep pipeline (issue-ahead 4) with register-double-buffered
// fragments: LDSM streams overlap HMMA bursts. (Unchanged from R14 — control.)
#define BM 128
#define BN 128
#define BK 32
#define AST 40                       // padded smem row stride in halves
#define NSTG 4                       // chunk buffers
#define STGA (BM*AST*2)              // 10240 bytes per A stage
#define STGB (BN*AST*2)              // 10240 bytes per B stage
#define STG  (STGA+STGB)             // 20480 bytes per stage
#define GSMEM (NSTG*STG)             // 81920 bytes dynamic smem

__device__ __forceinline__ void ldsm4(uint32_t& r0, uint32_t& r1, uint32_t& r2, uint32_t& r3,
                                      uint32_t addr) {
    asm volatile("ldmatrix.sync.aligned.m8n8.x4.shared.b16 {%0,%1,%2,%3}, [%4];"
                 : "=r"(r0), "=r"(r1), "=r"(r2), "=r"(r3) : "r"(addr));
}

extern __shared__ char gsm[];

__global__ void __launch_bounds__(256, 2) gemm1p_kernel(
    const __half* __restrict__ A, const __half* __restrict__ B,
    float* __restrict__ C, int M, int N, int K)
{
    const uint32_t sbase = (uint32_t)__cvta_generic_to_shared(gsm);

    const int tid  = threadIdx.x;
    const int warp = tid >> 5, lane = tid & 31;
    const int wm = warp & 3, wn = warp >> 2;      // 4 x 2 warp grid
    const int g  = lane >> 2, tg = lane & 3;
    const int bm = blockIdx.y * BM;
    const int bn = blockIdx.x * BN;
    const int KT = K / BK;                        // k-chunks (K=1024 -> 32)
    const int lr = tid >> 2;          // 0..63
    const int lc = (tid & 3) * 8;     // 0,8,16,24 halves

    const uint32_t dA0 = (lr * AST + lc) * 2;
    const uint32_t dA1 = ((lr + 64) * AST + lc) * 2;

    const int n0 = bn + lr, n1 = bn + lr + 64;
    const int p0 = (n0 < N) ? 16 : 0;
    const int p1 = (n1 < N) ? 16 : 0;
    const __half* pA0 = A + (uint32_t)(bm + lr) * (uint32_t)K + lc;
    const __half* pA1 = A + (uint32_t)(bm + lr + 64) * (uint32_t)K + lc;
    const __half* pB0 = B + (uint32_t)((n0 < N) ? n0 : N - 1) * (uint32_t)K + lc;
    const __half* pB1 = B + (uint32_t)((n1 < N) ? n1 : N - 1) * (uint32_t)K + lc;

    auto ISSUE = [&](int chunk) {
        int kk = chunk * BK;
        uint32_t st = sbase + (chunk & (NSTG - 1)) * STG;
        asm volatile("cp.async.cg.shared.global [%0], [%1], 16;\n"
                     :: "r"(st + dA0), "l"(pA0 + kk));
        asm volatile("cp.async.cg.shared.global [%0], [%1], 16;\n"
                     :: "r"(st + dA1), "l"(pA1 + kk));
        asm volatile("cp.async.cg.shared.global [%0], [%1], 16, %2;\n"
                     :: "r"(st + STGA + dA0), "l"(pB0 + kk), "r"(p0));
        asm volatile("cp.async.cg.shared.global [%0], [%1], 16, %2;\n"
                     :: "r"(st + STGA + dA1), "l"(pB1 + kk), "r"(p1));
        asm volatile("cp.async.commit_group;\n");
    };

    float acc[2][8][4];
#pragma unroll
    for (int i = 0; i < 2; i++)
#pragma unroll
        for (int j = 0; j < 8; j++)
#pragma unroll
            for (int q = 0; q < 4; q++) acc[i][j][q] = 0.f;

    const uint32_t a_row = wm * 32 + (lane & 15);
    const uint32_t a_ko  = (lane >> 4) << 3;
    const uint32_t b_row = wn * 64 + (lane & 7) + ((lane & 16) >> 1);
    const uint32_t b_ko  = (lane & 8);

    uint32_t ra0[2][4], ra1[2][4];
    uint32_t rb0[8][2], rb1[8][2];

    auto LOADA = [&](uint32_t (&r)[2][4], uint32_t Ab, int ks) {
#pragma unroll
        for (int mi = 0; mi < 2; ++mi) {
            uint32_t addr = Ab + ((a_row + mi * 16) * AST + ks * 16 + a_ko) * 2;
            ldsm4(r[mi][0], r[mi][1], r[mi][2], r[mi][3], addr);
        }
    };
    auto LOADB = [&](uint32_t (&r)[8][2], uint32_t Bb, int ks) {
#pragma unroll
        for (int ni2 = 0; ni2 < 4; ++ni2) {
            uint32_t addr = Bb + ((b_row + ni2 * 16) * AST + ks * 16 + b_ko) * 2;
            ldsm4(r[2*ni2][0], r[2*ni2][1], r[2*ni2+1][0], r[2*ni2+1][1], addr);
        }
    };
    auto MMA = [&](uint32_t (&rra)[2][4], uint32_t (&rrb)[8][2]) {
#pragma unroll
        for (int mi = 0; mi < 2; ++mi)
#pragma unroll
            for (int ni = 0; ni < 8; ++ni)
                asm volatile(
                    "mma.sync.aligned.m16n8k16.row.col.f32.f16.f16.f32 "
                    "{%0,%1,%2,%3},{%4,%5,%6,%7},{%8,%9},{%0,%1,%2,%3};\n"
                    : "+f"(acc[mi][ni][0]), "+f"(acc[mi][ni][1]),
                      "+f"(acc[mi][ni][2]), "+f"(acc[mi][ni][3])
                    : "r"(rra[mi][0]), "r"(rra[mi][1]), "r"(rra[mi][2]), "r"(rra[mi][3]),
                      "r"(rrb[ni][0]), "r"(rrb[ni][1]));
    };

    ISSUE(0); ISSUE(1); ISSUE(2); ISSUE(3);
    asm volatile("cp.async.wait_group 2;\n" ::: "memory");
    __syncthreads();
    LOADA(ra0, sbase, 0);
    LOADB(rb0, sbase + STGA, 0);

    for (int it = 0; it < KT; ++it) {
        const uint32_t st = sbase + (it & (NSTG - 1)) * STG;

        LOADA(ra1, st, 1);
        LOADB(rb1, st + STGA, 1);
        MMA(ra0, rb0);

        if (it + 1 < KT) {
            const uint32_t stn = sbase + ((it + 1) & (NSTG - 1)) * STG;
            LOADA(ra0, stn, 0);
            LOADB(rb0, stn + STGA, 0);
        }
        MMA(ra1, rb1);

        if (it + 3 >= KT) asm volatile("cp.async.wait_group 0;\n" ::: "memory");
        else              asm volatile("cp.async.wait_group 1;\n" ::: "memory");
        __syncthreads();
        if (it + 4 < KT) ISSUE(it + 4);
    }

#pragma unroll
    for (int mi = 0; mi < 2; ++mi) {
        int r0 = bm + wm * 32 + mi * 16 + g;
#pragma unroll
        for (int ni = 0; ni < 8; ++ni) {
            int c0 = bn + wn * 64 + ni * 8 + tg * 2;
            if (c0 < N) {
                *(float2*)(C + (size_t)r0       * N + c0) = make_float2(acc[mi][ni][0], acc[mi][ni][1]);
                *(float2*)(C + (size_t)(r0 + 8) * N + c0) = make_float2(acc[mi][ni][2], acc[mi][ni][3]);
            }
        }
    }
}

// ---------------- fused gate (conv+silu+repack, fp16 out) + decay ----------------
#define NGATE (MMR*DD/4)
#define NDEC  (BB*TT*HH)
__global__ void gatedecay_kernel(const float* __restrict__ conv_w,
                                 const float* __restrict__ conv_b,
                                 const float* __restrict__ dp) {
    int i = blockIdx.x * blockDim.x + threadIdx.x;
    if (i < NGATE) {
        // gate: thread = one channel d x 4 consecutive t; outputs share 7 k-taps
        int d   = i & (DD - 1);
        int bt4 = i >> 10;
        int t0  = (bt4 & (TT/4 - 1)) * 4;
        int b   = bt4 >> 9;

        const float* kcol = g_proj + 2 * DD + d;
        const size_t rowstride = NPJ;
        const size_t base = (size_t)(b * TT) * rowstride;

        float kv[7];
#pragma unroll
        for (int u = 0; u < 7; ++u) {
            int tt = t0 - 6 + u;
            kv[u] = (tt >= 0) ? kcol[base + (size_t)tt * rowstride] : 0.f;
        }

        float4 cw = *(const float4*)(conv_w + d * 4);
        const float cwj[4] = {cw.x, cw.y, cw.z, cw.w};
        float cb = conv_b[d];

        int h = d >> 6, kk = d & 63;
        __half* vout = g_vbuf + ((size_t)(b * HH + h) * TT) * KH + kk;
        const float* vcol = g_proj + DD + d;

#pragma unroll
        for (int q = 0; q < 4; ++q) {
            float ko = cb;
#pragma unroll
            for (int j = 0; j < 4; ++j)
                ko = fmaf(cwj[j], kv[q + j], ko);
            float sk = ko / (1.f + __expf(-ko));
            float v  = vcol[base + (size_t)(t0 + q) * rowstride];
            vout[(size_t)(t0 + q) * KH] = __float2half_rn(v * sk * SCALE_V);
        }
    } else {
        int idx = i - NGATE;
        if (idx >= NDEC) return;
        int h  = idx & (HH - 1);
        int bt = idx >> 4;
        float wv = g_proj[(size_t)bt * NPJ + 3 * DD + h];
        float gg = 1.f / (1.f + expf(-(dp[h] + wv)));
        float a  = expf(-8.f * (1.f - gg) - 0.1f);     // exp(log_decay), <= exp(-0.1)
        int b = bt >> 11, t = bt & (TT - 1);
        g_adec[(b * HH + h) * TT + t] = a;
    }
}

// ---------------- chunked scan: fused silu(r)*y -> fp16 g + GN partials ----------------
__global__ void scan_kernel() {
    const int c  = blockIdx.x & (NCH - 1);
    const int bh = blockIdx.x >> 5;
    const int b  = bh >> 4, h = bh & (HH - 1);
    const int k  = threadIdx.x;                          // 0..63
    const int t0 = c * SCH;
    int s0 = t0 - SLB; if (s0 < 0) s0 = 0;
    const __half* vp = g_vbuf + (size_t)bh * TT * KH;
    const float* ap = g_adec + (size_t)bh * TT;
    const int col = h * KH + k;

    float y = 0.f;
    for (int s = s0; s < t0; s += 4) {                   // lookback warm-up
        float4 a4 = *(const float4*)(ap + s);
        float v0 = __half2float(vp[(size_t)(s + 0) * KH + k]);
        float v1 = __half2float(vp[(size_t)(s + 1) * KH + k]);
        float v2 = __half2float(vp[(size_t)(s + 2) * KH + k]);
        float v3 = __half2float(vp[(size_t)(s + 3) * KH + k]);
        y = fmaf(a4.x, y, v0);
        y = fmaf(a4.y, y, v1);
        y = fmaf(a4.z, y, v2);
        y = fmaf(a4.w, y, v3);
    }

    float s1 = 0.f, s2 = 0.f;
    for (int sm = t0; sm < t0 + SCH; sm += 4) {
        float4 a4 = *(const float4*)(ap + sm);
        float aa[4] = {a4.x, a4.y, a4.z, a4.w};
        float vv[4], rr[4];
#pragma unroll
        for (int j = 0; j < 4; ++j) {
            vv[j] = __half2float(vp[(size_t)(sm + j) * KH + k]);
            rr[j] = g_proj[(size_t)(b * TT + sm + j) * NPJ + col];
        }
#pragma unroll
        for (int j = 0; j < 4; ++j) {
            y = fmaf(aa[j], y, vv[j]);
            float r  = rr[j];
            float sr = r / (1.f + __expf(-r));
            float gv = sr * y;
            g_gh[(size_t)(b * TT + sm + j) * DD + col] = __float2half_rn(gv);
            s1 += gv;
            s2 = fmaf(gv, gv, s2);
        }
    }

    __shared__ float rs1[64], rs2[64];
    rs1[k] = s1; rs2[k] = s2;
    __syncthreads();
    for (int off = 32; off > 0; off >>= 1) {
        if (k < off) { rs1[k] += rs1[k + off]; rs2[k] += rs2[k + off]; }
        __syncthreads();
    }
    if (k == 0) g_psum[bh * NCH + c] = make_float2(rs1[0], rs2[0]);
}

// ---------------- GroupNorm statistics (deterministic combine) ----------------
__global__ void stats_kernel() {
    int gi = threadIdx.x;
    if (gi >= BB * HH) return;
    float s1 = 0.f, s2 = 0.f;
    for (int c = 0; c < NCH; ++c) {
        float2 p = g_psum[gi * NCH + c];
        s1 += p.x; s2 += p.y;
    }
    const float inv = 1.f / (float)(KH * TT);
    float mean = s1 * inv;
    float var  = s2 * inv - mean * mean;
    g_stats[gi] = make_float2(mean, rsqrtf(var + 1e-5f));
}

// ---------------- normalize + affine, in place on fp16 g (x4) ----------------
__global__ void normcvt_kernel(const float* __restrict__ gn_w, const float* __restrict__ gn_b) {
    int i4 = blockIdx.x * blockDim.x + threadIdx.x;
    if (i4 >= MMR * DD / 4) return;
    int idx = i4 * 4;
    int d  = idx & (DD - 1);
    int bt = idx >> 10;
    int b  = bt >> 11;
    int h  = d >> 6;
    float2 st = g_stats[b * HH + h];
    __half2* ph = (__half2*)(g_gh + idx);
    float2 g0 = __half22float2(ph[0]);
    float2 g1 = __half22float2(ph[1]);
    float4 w4 = *(const float4*)(gn_w + d);
    float4 b4 = *(const float4*)(gn_b + d);
    ph[0] = __halves2half2(__float2half_rn(fmaf((g0.x - st.x) * st.y, w4.x, b4.x)),
                           __float2half_rn(fmaf((g0.y - st.x) * st.y, w4.y, b4.y)));
    ph[1] = __halves2half2(__float2half_rn(fmaf((g1.x - st.x) * st.y, w4.z, b4.z)),
                           __float2half_rn(fmaf((g1.y - st.x) * st.y, w4.w, b4.w)));
}

// ---------------- launch ----------------
extern "C" void kernel_launch(void* const* d_in, const int* in_sizes, int n_in,
                              void* d_out, int out_size) {
    const float* x      = (const float*)d_in[0];
    const float* W_in   = (const float*)d_in[1];
    const float* conv_w = (const float*)d_in[2];
    const float* conv_b = (const float*)d_in[3];
    const float* dp     = (const float*)d_in[4];
    const float* gn_w   = (const float*)d_in[5];
    const float* gn_b   = (const float*)d_in[6];
    const float* W_out  = (const float*)d_in[7];
    float* out = (float*)d_out;
    (void)in_sizes; (void)n_in; (void)out_size;

    void *pxh, *pwih, *pwoh, *pproj, *pgh;
    cudaGetSymbolAddress(&pxh,  g_xh);
    cudaGetSymbolAddress(&pwih, g_wih);
    cudaGetSymbolAddress(&pwoh, g_woh);
    cudaGetSymbolAddress(&pproj, g_proj);
    cudaGetSymbolAddress(&pgh,  g_gh);

    cudaFuncSetAttribute(gemm1p_kernel,
                         cudaFuncAttributeMaxDynamicSharedMemorySize, GSMEM);

    const int TPB = 256;
    const int NCVT = N4X + N4WI + N4WO;
    cvt3_kernel<<<(NCVT + TPB-1)/TPB, TPB>>>((const float4*)x,
                                             (const float4*)W_in,
                                             (const float4*)W_out);

    // GEMM1: proj = x @ W_in^T (single-pass fp16, fp32 accum)
    dim3 gg1((NPJ + BN - 1)/BN, MMR/BM);
    gemm1p_kernel<<<gg1, 256, GSMEM>>>((__half*)pxh, (__half*)pwih,
                                       (float*)pproj, MMR, NPJ, DD);

    gatedecay_kernel<<<(NGATE + NDEC + TPB-1)/TPB, TPB>>>(conv_w, conv_b, dp);
    scan_kernel <<<BB*HH*NCH, 64>>>();
    stats_kernel<<<1, 32>>>();
    normcvt_kernel<<<(MMR*DD/4 + TPB-1)/TPB, TPB>>>(gn_w, gn_b);

    // GEMM2: out = g_norm @ W_out^T
    dim3 gg2(DD/BN, MMR/BM);
    gemm1p_kernel<<<gg2, 256, GSMEM>>>((__half*)pgh, (__half*)pwoh,
                                       out, MMR, DD, DD);
}

// round 17
// speedup vs baseline: 1.2872x; 1.0388x over previous
#include <cuda_runtime.h>
#include <cuda_fp16.h>
#include <cstdint>
#include <cstddef>

// ---------------- problem constants ----------------
#define BB   2
#define TT   2048
#define DD   1024
#define HH   16
#define KH   64          // D / H
#define NPJ  3088        // 3*D + H
#define MMR  4096        // B*T
#define SCALE_V 0.03125f // 1/sqrt(D)
#define SCH  32          // scan chunk (smaller -> more blocks -> higher occupancy)
#define SLB  128         // scan lookback (err <= e^-12.8 ~ 2.7e-6)
#define NCH  (TT/SCH)    // 64
#define NCHS 6           // log2(NCH)

// ---------------- scratch (__device__ globals; no allocations) ----------------
__device__ __half g_xh [MMR*DD];
__device__ __half g_wih[NPJ*DD];
__device__ __half g_woh[DD*DD];
__device__ float  g_proj[(size_t)MMR*NPJ]; // (B*T, 3D+H)
__device__ __half g_vbuf[MMR*DD];          // (B,H,T,K) gated v * scale (fp16)
__device__ float  g_adec[BB*HH*TT];        // (B,H,T) decay multiplier
__device__ __half g_gh [MMR*DD];           // g = silu(r)*y (fp16); normalized in place
__device__ float2 g_psum[BB*HH*NCH];       // partial (sum, sumsq) per group-chunk
__device__ float2 g_stats[BB*HH];          // (mean, rstd)

// ---------------- fused fp32 -> fp16 conversion for x, W_in, W_out ----------------
#define N4X (MMR*DD/4)
#define N4WI (NPJ*DD/4)
#define N4WO (DD*DD/4)
__global__ void cvt3_kernel(const float4* __restrict__ x,
                            const float4* __restrict__ wi,
                            const float4* __restrict__ wo) {
    int i = blockIdx.x * blockDim.x + threadIdx.x;
    const float4* src;
    __half2* dst;
    int j;
    if (i < N4X)                { src = x;  dst = (__half2*)g_xh;  j = i; }
    else if (i < N4X + N4WI)    { src = wi; dst = (__half2*)g_wih; j = i - N4X; }
    else if (i < N4X+N4WI+N4WO) { src = wo; dst = (__half2*)g_woh; j = i - N4X - N4WI; }
    else return;
    float4 v = src[j];
    dst[2*j]   = __halves2half2(__float2half_rn(v.x), __float2half_rn(v.y));
    dst[2*j+1] = __halves2half2(__float2half_rn(v.z), __float2half_rn(v.w));
}

// ---------------- single-pass fp16 GEMM: C = A*B^T (fp32 accum) ----------------
// 128x128 CTA tile, 256 threads, 4x2 warps of 32x64.
// Barrier-certified deep pipeline (issue-ahead 4) with register-double-buffered
// fragments: LDSM streams overlap HMMA bursts. (Unchanged — control.)
#define BM 128
#define BN 128
#define BK 32
#define AST 40                       // padded smem row stride in halves
#define NSTG 4                       // chunk buffers
#define STGA (BM*AST*2)              // 10240 bytes per A stage
#define STGB (BN*AST*2)              // 10240 bytes per B stage
#define STG  (STGA+STGB)             // 20480 bytes per stage
#define GSMEM (NSTG*STG)             // 81920 bytes dynamic smem

__device__ __forceinline__ void ldsm4(uint32_t& r0, uint32_t& r1, uint32_t& r2, uint32_t& r3,
                                      uint32_t addr) {
    asm volatile("ldmatrix.sync.aligned.m8n8.x4.shared.b16 {%0,%1,%2,%3}, [%4];"
                 : "=r"(r0), "=r"(r1), "=r"(r2), "=r"(r3) : "r"(addr));
}

extern __shared__ char gsm[];

__global__ void __launch_bounds__(256, 2) gemm1p_kernel(
    const __half* __restrict__ A, const __half* __restrict__ B,
    float* __restrict__ C, int M, int N, int K)
{
    const uint32_t sbase = (uint32_t)__cvta_generic_to_shared(gsm);

    const int tid  = threadIdx.x;
    const int warp = tid >> 5, lane = tid & 31;
    const int wm = warp & 3, wn = warp >> 2;      // 4 x 2 warp grid
    const int g  = lane >> 2, tg = lane & 3;
    const int bm = blockIdx.y * BM;
    const int bn = blockIdx.x * BN;
    const int KT = K / BK;                        // k-chunks (K=1024 -> 32)
    const int lr = tid >> 2;          // 0..63
    const int lc = (tid & 3) * 8;     // 0,8,16,24 halves

    const uint32_t dA0 = (lr * AST + lc) * 2;
    const uint32_t dA1 = ((lr + 64) * AST + lc) * 2;

    const int n0 = bn + lr, n1 = bn + lr + 64;
    const int p0 = (n0 < N) ? 16 : 0;
    const int p1 = (n1 < N) ? 16 : 0;
    const __half* pA0 = A + (uint32_t)(bm + lr) * (uint32_t)K + lc;
    const __half* pA1 = A + (uint32_t)(bm + lr + 64) * (uint32_t)K + lc;
    const __half* pB0 = B + (uint32_t)((n0 < N) ? n0 : N - 1) * (uint32_t)K + lc;
    const __half* pB1 = B + (uint32_t)((n1 < N) ? n1 : N - 1) * (uint32_t)K + lc;

    auto ISSUE = [&](int chunk) {
        int kk = chunk * BK;
        uint32_t st = sbase + (chunk & (NSTG - 1)) * STG;
        asm volatile("cp.async.cg.shared.global [%0], [%1], 16;\n"
                     :: "r"(st + dA0), "l"(pA0 + kk));
        asm volatile("cp.async.cg.shared.global [%0], [%1], 16;\n"
                     :: "r"(st + dA1), "l"(pA1 + kk));
        asm volatile("cp.async.cg.shared.global [%0], [%1], 16, %2;\n"
                     :: "r"(st + STGA + dA0), "l"(pB0 + kk), "r"(p0));
        asm volatile("cp.async.cg.shared.global [%0], [%1], 16, %2;\n"
                     :: "r"(st + STGA + dA1), "l"(pB1 + kk), "r"(p1));
        asm volatile("cp.async.commit_group;\n");
    };

    float acc[2][8][4];
#pragma unroll
    for (int i = 0; i < 2; i++)
#pragma unroll
        for (int j = 0; j < 8; j++)
#pragma unroll
            for (int q = 0; q < 4; q++) acc[i][j][q] = 0.f;

    const uint32_t a_row = wm * 32 + (lane & 15);
    const uint32_t a_ko  = (lane >> 4) << 3;
    const uint32_t b_row = wn * 64 + (lane & 7) + ((lane & 16) >> 1);
    const uint32_t b_ko  = (lane & 8);

    uint32_t ra0[2][4], ra1[2][4];
    uint32_t rb0[8][2], rb1[8][2];

    auto LOADA = [&](uint32_t (&r)[2][4], uint32_t Ab, int ks) {
#pragma unroll
        for (int mi = 0; mi < 2; ++mi) {
            uint32_t addr = Ab + ((a_row + mi * 16) * AST + ks * 16 + a_ko) * 2;
            ldsm4(r[mi][0], r[mi][1], r[mi][2], r[mi][3], addr);
        }
    };
    auto LOADB = [&](uint32_t (&r)[8][2], uint32_t Bb, int ks) {
#pragma unroll
        for (int ni2 = 0; ni2 < 4; ++ni2) {
            uint32_t addr = Bb + ((b_row + ni2 * 16) * AST + ks * 16 + b_ko) * 2;
            ldsm4(r[2*ni2][0], r[2*ni2][1], r[2*ni2+1][0], r[2*ni2+1][1], addr);
        }
    };
    auto MMA = [&](uint32_t (&rra)[2][4], uint32_t (&rrb)[8][2]) {
#pragma unroll
        for (int mi = 0; mi < 2; ++mi)
#pragma unroll
            for (int ni = 0; ni < 8; ++ni)
                asm volatile(
                    "mma.sync.aligned.m16n8k16.row.col.f32.f16.f16.f32 "
                    "{%0,%1,%2,%3},{%4,%5,%6,%7},{%8,%9},{%0,%1,%2,%3};\n"
                    : "+f"(acc[mi][ni][0]), "+f"(acc[mi][ni][1]),
                      "+f"(acc[mi][ni][2]), "+f"(acc[mi][ni][3])
                    : "r"(rra[mi][0]), "r"(rra[mi][1]), "r"(rra[mi][2]), "r"(rra[mi][3]),
                      "r"(rrb[ni][0]), "r"(rrb[ni][1]));
    };

    ISSUE(0); ISSUE(1); ISSUE(2); ISSUE(3);
    asm volatile("cp.async.wait_group 2;\n" ::: "memory");
    __syncthreads();
    LOADA(ra0, sbase, 0);
    LOADB(rb0, sbase + STGA, 0);

    for (int it = 0; it < KT; ++it) {
        const uint32_t st = sbase + (it & (NSTG - 1)) * STG;

        LOADA(ra1, st, 1);
        LOADB(rb1, st + STGA, 1);
        MMA(ra0, rb0);

        if (it + 1 < KT) {
            const uint32_t stn = sbase + ((it + 1) & (NSTG - 1)) * STG;
            LOADA(ra0, stn, 0);
            LOADB(rb0, stn + STGA, 0);
        }
        MMA(ra1, rb1);

        if (it + 3 >= KT) asm volatile("cp.async.wait_group 0;\n" ::: "memory");
        else              asm volatile("cp.async.wait_group 1;\n" ::: "memory");
        __syncthreads();
        if (it + 4 < KT) ISSUE(it + 4);
    }

#pragma unroll
    for (int mi = 0; mi < 2; ++mi) {
        int r0 = bm + wm * 32 + mi * 16 + g;
#pragma unroll
        for (int ni = 0; ni < 8; ++ni) {
            int c0 = bn + wn * 64 + ni * 8 + tg * 2;
            if (c0 < N) {
                *(float2*)(C + (size_t)r0       * N + c0) = make_float2(acc[mi][ni][0], acc[mi][ni][1]);
                *(float2*)(C + (size_t)(r0 + 8) * N + c0) = make_float2(acc[mi][ni][2], acc[mi][ni][3]);
            }
        }
    }
}

// ---------------- fused gate (conv+silu+repack, fp16 out) + decay ----------------
#define NGATE (MMR*DD/4)
#define NDEC  (BB*TT*HH)
__global__ void gatedecay_kernel(const float* __restrict__ conv_w,
                                 const float* __restrict__ conv_b,
                                 const float* __restrict__ dp) {
    int i = blockIdx.x * blockDim.x + threadIdx.x;
    if (i < NGATE) {
        // gate: thread = one channel d x 4 consecutive t; outputs share 7 k-taps
        int d   = i & (DD - 1);
        int bt4 = i >> 10;
        int t0  = (bt4 & (TT/4 - 1)) * 4;
        int b   = bt4 >> 9;

        const float* kcol = g_proj + 2 * DD + d;
        const size_t rowstride = NPJ;
        const size_t base = (size_t)(b * TT) * rowstride;

        float kv[7];
#pragma unroll
        for (int u = 0; u < 7; ++u) {
            int tt = t0 - 6 + u;
            kv[u] = (tt >= 0) ? kcol[base + (size_t)tt * rowstride] : 0.f;
        }

        float4 cw = *(const float4*)(conv_w + d * 4);
        const float cwj[4] = {cw.x, cw.y, cw.z, cw.w};
        float cb = conv_b[d];

        int h = d >> 6, kk = d & 63;
        __half* vout = g_vbuf + ((size_t)(b * HH + h) * TT) * KH + kk;
        const float* vcol = g_proj + DD + d;

#pragma unroll
        for (int q = 0; q < 4; ++q) {
            float ko = cb;
#pragma unroll
            for (int j = 0; j < 4; ++j)
                ko = fmaf(cwj[j], kv[q + j], ko);
            float sk = ko / (1.f + __expf(-ko));
            float v  = vcol[base + (size_t)(t0 + q) * rowstride];
            vout[(size_t)(t0 + q) * KH] = __float2half_rn(v * sk * SCALE_V);
        }
    } else {
        int idx = i - NGATE;
        if (idx >= NDEC) return;
        int h  = idx & (HH - 1);
        int bt = idx >> 4;
        float wv = g_proj[(size_t)bt * NPJ + 3 * DD + h];
        float gg = 1.f / (1.f + expf(-(dp[h] + wv)));
        float a  = expf(-8.f * (1.f - gg) - 0.1f);     // exp(log_decay), <= exp(-0.1)
        int b = bt >> 11, t = bt & (TT - 1);
        g_adec[(b * HH + h) * TT + t] = a;
    }
}

// ---------------- chunked scan: fused silu(r)*y -> fp16 g + GN partials ----------------
__global__ void scan_kernel() {
    const int c  = blockIdx.x & (NCH - 1);
    const int bh = blockIdx.x >> NCHS;
    const int b  = bh >> 4, h = bh & (HH - 1);
    const int k  = threadIdx.x;                          // 0..63
    const int t0 = c * SCH;
    int s0 = t0 - SLB; if (s0 < 0) s0 = 0;
    const __half* vp = g_vbuf + (size_t)bh * TT * KH;
    const float* ap = g_adec + (size_t)bh * TT;
    const int col = h * KH + k;

    float y = 0.f;
    for (int s = s0; s < t0; s += 4) {                   // lookback warm-up
        float4 a4 = *(const float4*)(ap + s);
        float v0 = __half2float(vp[(size_t)(s + 0) * KH + k]);
        float v1 = __half2float(vp[(size_t)(s + 1) * KH + k]);
        float v2 = __half2float(vp[(size_t)(s + 2) * KH + k]);
        float v3 = __half2float(vp[(size_t)(s + 3) * KH + k]);
        y = fmaf(a4.x, y, v0);
        y = fmaf(a4.y, y, v1);
        y = fmaf(a4.z, y, v2);
        y = fmaf(a4.w, y, v3);
    }

    float s1 = 0.f, s2 = 0.f;
    for (int sm = t0; sm < t0 + SCH; sm += 4) {
        float4 a4 = *(const float4*)(ap + sm);
        float aa[4] = {a4.x, a4.y, a4.z, a4.w};
        float vv[4], rr[4];
#pragma unroll
        for (int j = 0; j < 4; ++j) {
            vv[j] = __half2float(vp[(size_t)(sm + j) * KH + k]);
            rr[j] = g_proj[(size_t)(b * TT + sm + j) * NPJ + col];
        }
#pragma unroll
        for (int j = 0; j < 4; ++j) {
            y = fmaf(aa[j], y, vv[j]);
            float r  = rr[j];
            float sr = r / (1.f + __expf(-r));
            float gv = sr * y;
            g_gh[(size_t)(b * TT + sm + j) * DD + col] = __float2half_rn(gv);
            s1 += gv;
            s2 = fmaf(gv, gv, s2);
        }
    }

    __shared__ float rs1[64], rs2[64];
    rs1[k] = s1; rs2[k] = s2;
    __syncthreads();
    for (int off = 32; off > 0; off >>= 1) {
        if (k < off) { rs1[k] += rs1[k + off]; rs2[k] += rs2[k + off]; }
        __syncthreads();
    }
    if (k == 0) g_psum[bh * NCH + c] = make_float2(rs1[0], rs2[0]);
}

// ---------------- GroupNorm statistics (deterministic combine) ----------------
__global__ void stats_kernel() {
    int gi = threadIdx.x;
    if (gi >= BB * HH) return;
    float s1 = 0.f, s2 = 0.f;
    for (int c = 0; c < NCH; ++c) {
        float2 p = g_psum[gi * NCH + c];
        s1 += p.x; s2 += p.y;
    }
    const float inv = 1.f / (float)(KH * TT);
    float mean = s1 * inv;
    float var  = s2 * inv - mean * mean;
    g_stats[gi] = make_float2(mean, rsqrtf(var + 1e-5f));
}

// ---------------- normalize + affine, in place on fp16 g (x8) ----------------
__global__ void normcvt_kernel(const float* __restrict__ gn_w, const float* __restrict__ gn_b) {
    int i8 = blockIdx.x * blockDim.x + threadIdx.x;
    if (i8 >= MMR * DD / 8) return;
    int idx = i8 * 8;
    int d  = idx & (DD - 1);
    int bt = idx >> 10;
    int b  = bt >> 11;
    int h  = d >> 6;                                   // d..d+7 same head (d % 8 == 0)
    float2 st = g_stats[b * HH + h];
    __half2* ph = (__half2*)(g_gh + idx);
    uint4 raw = *(uint4*)ph;
    __half2* hp = (__half2*)&raw;
    const float4 w0 = *(const float4*)(gn_w + d);
    const float4 w1 = *(const float4*)(gn_w + d + 4);
    const float4 b0 = *(const float4*)(gn_b + d);
    const float4 b1 = *(const float4*)(gn_b + d + 4);
    float2 gv[4];
#pragma unroll
    for (int u = 0; u < 4; ++u) gv[u] = __half22float2(hp[u]);
    hp[0] = __halves2half2(__float2half_rn(fmaf((gv[0].x - st.x) * st.y, w0.x, b0.x)),
                           __float2half_rn(fmaf((gv[0].y - st.x) * st.y, w0.y, b0.y)));
    hp[1] = __halves2half2(__float2half_rn(fmaf((gv[1].x - st.x) * st.y, w0.z, b0.z)),
                           __float2half_rn(fmaf((gv[1].y - st.x) * st.y, w0.w, b0.w)));
    hp[2] = __halves2half2(__float2half_rn(fmaf((gv[2].x - st.x) * st.y, w1.x, b1.x)),
                           __float2half_rn(fmaf((gv[2].y - st.x) * st.y, w1.y, b1.y)));
    hp[3] = __halves2half2(__float2half_rn(fmaf((gv[3].x - st.x) * st.y, w1.z, b1.z)),
                           __float2half_rn(fmaf((gv[3].y - st.x) * st.y, w1.w, b1.w)));
    *(uint4*)ph = raw;
}

// ---------------- launch ----------------
extern "C" void kernel_launch(void* const* d_in, const int* in_sizes, int n_in,
                              void* d_out, int out_size) {
    const float* x      = (const float*)d_in[0];
    const float* W_in   = (const float*)d_in[1];
    const float* conv_w = (const float*)d_in[2];
    const float* conv_b = (const float*)d_in[3];
    const float* dp     = (const float*)d_in[4];
    const float* gn_w   = (const float*)d_in[5];
    const float* gn_b   = (const float*)d_in[6];
    const float* W_out  = (const float*)d_in[7];
    float* out = (float*)d_out;
    (void)in_sizes; (void)n_in; (void)out_size;

    void *pxh, *pwih, *pwoh, *pproj, *pgh;
    cudaGetSymbolAddress(&pxh,  g_xh);
    cudaGetSymbolAddress(&pwih, g_wih);
    cudaGetSymbolAddress(&pwoh, g_woh);
    cudaGetSymbolAddress(&pproj, g_proj);
    cudaGetSymbolAddress(&pgh,  g_gh);

    cudaFuncSetAttribute(gemm1p_kernel,
                         cudaFuncAttributeMaxDynamicSharedMemorySize, GSMEM);

    const int TPB = 256;
    const int NCVT = N4X + N4WI + N4WO;
    cvt3_kernel<<<(NCVT + TPB-1)/TPB, TPB>>>((const float4*)x,
                                             (const float4*)W_in,
                                             (const float4*)W_out);

    // GEMM1: proj = x @ W_in^T (single-pass fp16, fp32 accum)
    dim3 gg1((NPJ + BN - 1)/BN, MMR/BM);
    gemm1p_kernel<<<gg1, 256, GSMEM>>>((__half*)pxh, (__half*)pwih,
                                       (float*)pproj, MMR, NPJ, DD);

    gatedecay_kernel<<<(NGATE + NDEC + TPB-1)/TPB, TPB>>>(conv_w, conv_b, dp);
    scan_kernel <<<BB*HH*NCH, 64>>>();
    stats_kernel<<<1, 32>>>();
    normcvt_kernel<<<(MMR*DD/8 + TPB-1)/TPB, TPB>>>(gn_w, gn_b);

    // GEMM2: out = g_norm @ W_out^T
    dim3 gg2(DD/BN, MMR/BM);
    gemm1p_kernel<<<gg2, 256, GSMEM>>>((__half*)pgh, (__half*)pwoh,
                                       out, MMR, DD, DD);
}